// round 6
// baseline (speedup 1.0000x reference)
#include <cuda_runtime.h>

// Problem constants
#define B_   2
#define P_   2048
#define M_   1024
#define H_   16
#define D_   64
#define NROWS (B_ * P_)          // 4096
#define QKV_N (3 * M_)           // 3072

// Scratch (device globals: no allocations allowed). 128B-aligned for float4 paths.
__device__ __align__(128) float g_qkv[(size_t)NROWS * QKV_N];   // [4096, 3072] : Q|K|V each [H,D]
__device__ __align__(128) float g_z  [(size_t)NROWS * M_];      // [4096, 1024]

// ---------------------------------------------------------------------------
// SGEMM: C[rows, N] = A[rows, K] @ B[K, N] + bias[N]
// 128x128 tile, BK=16, 256 threads, 8x8 per thread.
// All dims divisible by tile sizes for this problem.
// ---------------------------------------------------------------------------
__global__ __launch_bounds__(256) void sgemm128(const float* __restrict__ A,
                                                const float* __restrict__ Bm,
                                                const float* __restrict__ bias,
                                                float* __restrict__ C,
                                                int N, int K)
{
    __shared__ float As[16][128];
    __shared__ float Bs[16][128];

    const int t    = threadIdx.x;
    const int brow = blockIdx.y * 128;
    const int bcol = blockIdx.x * 128;
    const int rs   = (t >> 4) << 3;   // row start within tile (0..120)
    const int cs   = (t & 15) << 3;   // col start within tile

    float acc[8][8];
#pragma unroll
    for (int i = 0; i < 8; i++)
#pragma unroll
        for (int j = 0; j < 8; j++) acc[i][j] = 0.0f;

    const float* Ap = A + (size_t)brow * K;
    const float* Bp = Bm + bcol;

    for (int k0 = 0; k0 < K; k0 += 16) {
        // Load A tile (128 rows x 16 k), store transposed As[k][row]
        for (int i = t; i < 512; i += 256) {
            int row = i >> 2, f4 = (i & 3) << 2;
            float4 v = *(const float4*)(Ap + (size_t)row * K + k0 + f4);
            As[f4 + 0][row] = v.x;
            As[f4 + 1][row] = v.y;
            As[f4 + 2][row] = v.z;
            As[f4 + 3][row] = v.w;
        }
        // Load B tile (16 k x 128 cols)
        for (int i = t; i < 512; i += 256) {
            int kr = i >> 5, f4 = (i & 31) << 2;
            *(float4*)(&Bs[kr][f4]) = *(const float4*)(Bp + (size_t)(k0 + kr) * N + f4);
        }
        __syncthreads();

#pragma unroll
        for (int kk = 0; kk < 16; kk++) {
            float a[8], bv[8];
            *(float4*)(a)      = *(const float4*)(&As[kk][rs]);
            *(float4*)(a + 4)  = *(const float4*)(&As[kk][rs + 4]);
            *(float4*)(bv)     = *(const float4*)(&Bs[kk][cs]);
            *(float4*)(bv + 4) = *(const float4*)(&Bs[kk][cs + 4]);
#pragma unroll
            for (int i = 0; i < 8; i++)
#pragma unroll
                for (int j = 0; j < 8; j++)
                    acc[i][j] = fmaf(a[i], bv[j], acc[i][j]);
        }
        __syncthreads();
    }

#pragma unroll
    for (int i = 0; i < 8; i++) {
        size_t roff = (size_t)(brow + rs + i) * N + bcol + cs;
#pragma unroll
        for (int j = 0; j < 8; j += 4) {
            float4 v;
            v.x = acc[i][j + 0] + bias[bcol + cs + j + 0];
            v.y = acc[i][j + 1] + bias[bcol + cs + j + 1];
            v.z = acc[i][j + 2] + bias[bcol + cs + j + 2];
            v.w = acc[i][j + 3] + bias[bcol + cs + j + 3];
            *(float4*)(C + roff + j) = v;
        }
    }
}

// ---------------------------------------------------------------------------
// Flash attention (causal), fp32. One CTA = (batch b, head h, 64-query tile).
// qkv layout: row (b*P + p) has 3072 floats: Q[H][D] | K[H][D] | V[H][D].
// 256 threads as 16x16 grid; thread computes 4x4 of S / 4x4 of O.
// smem: Qs[64][64], Ks[64][65], Ps[64][64], Vs[64][64] (dynamic, ~64KB)
// Ks uses odd stride 65 -> scalar LDS of K columns is conflict-free; the tile
// store therefore MUST be scalar (a float4 STS at odd stride is misaligned).
// ---------------------------------------------------------------------------
#define SMEM_ATTN ((4096 + 4160 + 4096 + 4096) * 4)

__global__ __launch_bounds__(256) void attn_kernel(const float* __restrict__ qkv,
                                                   float* __restrict__ Z)
{
    extern __shared__ float sm[];
    float* Qs = sm;                          // [64][64]
    float* Ks = sm + 4096;                   // [64][65]
    float* Ps = sm + 4096 + 4160;            // [64][64]
    float* Vs = sm + 4096 + 4160 + 4096;     // [64][64]

    const int qt = blockIdx.x;   // query tile 0..31
    const int h  = blockIdx.y;   // head
    const int b  = blockIdx.z;   // batch
    const int t  = threadIdx.x;
    const int rs = (t >> 4) << 2;   // 4-row group
    const int cs = (t & 15) << 2;   // 4-col group

    const size_t rstride = QKV_N;
    const float* qbase = qkv + ((size_t)(b * P_ + qt * 64)) * rstride + h * D_;
    const float* kbase = qkv + (size_t)b * P_ * rstride + M_ + h * D_;
    const float* vbase = kbase + M_;

    // Load Q tile, pre-scaled by 1/sqrt(D)=0.125
    for (int i = t; i < 64 * 16; i += 256) {
        int row = i >> 4, f4 = (i & 15) << 2;
        float4 v = *(const float4*)(qbase + (size_t)row * rstride + f4);
        v.x *= 0.125f; v.y *= 0.125f; v.z *= 0.125f; v.w *= 0.125f;
        *(float4*)(&Qs[row * 64 + f4]) = v;
    }

    float m[4], l[4], O[4][4];
#pragma unroll
    for (int i = 0; i < 4; i++) {
        m[i] = -1e30f; l[i] = 0.0f;
#pragma unroll
        for (int j = 0; j < 4; j++) O[i][j] = 0.0f;
    }

    for (int kb = 0; kb <= qt; kb++) {
        // Load K, V tiles. K store is SCALAR (odd stride 65 => float4 STS would
        // be misaligned for odd rows). Scalar STS at stride 65 is conflict-free.
        for (int i = t; i < 64 * 16; i += 256) {
            int row = i >> 4, f4 = (i & 15) << 2;
            size_t g = (size_t)(kb * 64 + row) * rstride + f4;
            float4 kv4 = *(const float4*)(kbase + g);
            Ks[row * 65 + f4 + 0] = kv4.x;
            Ks[row * 65 + f4 + 1] = kv4.y;
            Ks[row * 65 + f4 + 2] = kv4.z;
            Ks[row * 65 + f4 + 3] = kv4.w;
            *(float4*)(&Vs[row * 64 + f4]) = *(const float4*)(vbase + g);
        }
        __syncthreads();

        // S = Q K^T (4x4 per thread)
        float s[4][4];
#pragma unroll
        for (int i = 0; i < 4; i++)
#pragma unroll
            for (int j = 0; j < 4; j++) s[i][j] = 0.0f;

#pragma unroll 4
        for (int d = 0; d < 64; d++) {
            float a[4], kv[4];
#pragma unroll
            for (int i = 0; i < 4; i++) a[i]  = Qs[(rs + i) * 64 + d];
#pragma unroll
            for (int j = 0; j < 4; j++) kv[j] = Ks[(cs + j) * 65 + d];
#pragma unroll
            for (int i = 0; i < 4; i++)
#pragma unroll
                for (int j = 0; j < 4; j++)
                    s[i][j] = fmaf(a[i], kv[j], s[i][j]);
        }

        if (kb == qt) {   // causal mask on diagonal tile
#pragma unroll
            for (int i = 0; i < 4; i++)
#pragma unroll
                for (int j = 0; j < 4; j++)
                    if (cs + j > rs + i) s[i][j] = -1e30f;
        }

        // Row max over the 16-lane groups (lanes 0-15 / 16-31 each hold one 4-row group)
        float tm[4];
#pragma unroll
        for (int i = 0; i < 4; i++)
            tm[i] = fmaxf(fmaxf(s[i][0], s[i][1]), fmaxf(s[i][2], s[i][3]));
#pragma unroll
        for (int off = 8; off >= 1; off >>= 1) {
#pragma unroll
            for (int i = 0; i < 4; i++)
                tm[i] = fmaxf(tm[i], __shfl_xor_sync(0xffffffffu, tm[i], off, 32));
        }

        float m_new[4], sc[4], rsum[4];
#pragma unroll
        for (int i = 0; i < 4; i++) {
            m_new[i] = fmaxf(m[i], tm[i]);
            sc[i]    = __expf(m[i] - m_new[i]);
        }
#pragma unroll
        for (int i = 0; i < 4; i++) {
            float r = 0.0f;
#pragma unroll
            for (int j = 0; j < 4; j++) {
                float p = __expf(s[i][j] - m_new[i]);
                s[i][j] = p;
                r += p;
            }
            rsum[i] = r;
        }
#pragma unroll
        for (int off = 8; off >= 1; off >>= 1) {
#pragma unroll
            for (int i = 0; i < 4; i++)
                rsum[i] += __shfl_xor_sync(0xffffffffu, rsum[i], off, 32);
        }
#pragma unroll
        for (int i = 0; i < 4; i++) {
            l[i] = l[i] * sc[i] + rsum[i];
            m[i] = m_new[i];
#pragma unroll
            for (int j = 0; j < 4; j++) O[i][j] *= sc[i];
        }

        // Stage P to smem for the PV product (stride 64, cs multiple of 4: aligned)
#pragma unroll
        for (int i = 0; i < 4; i++) {
            float4 v = make_float4(s[i][0], s[i][1], s[i][2], s[i][3]);
            *(float4*)(&Ps[(rs + i) * 64 + cs]) = v;
        }
        __syncthreads();

        // O += P @ V
#pragma unroll 4
        for (int kk = 0; kk < 64; kk++) {
            float4 v4 = *(const float4*)(&Vs[kk * 64 + cs]);
            float pv[4];
#pragma unroll
            for (int i = 0; i < 4; i++) pv[i] = Ps[(rs + i) * 64 + kk];
#pragma unroll
            for (int i = 0; i < 4; i++) {
                O[i][0] = fmaf(pv[i], v4.x, O[i][0]);
                O[i][1] = fmaf(pv[i], v4.y, O[i][1]);
                O[i][2] = fmaf(pv[i], v4.z, O[i][2]);
                O[i][3] = fmaf(pv[i], v4.w, O[i][3]);
            }
        }
        __syncthreads();
    }

    // Normalize + store to Z[b,p,h,d]
    size_t zbase = ((size_t)(b * P_) + qt * 64) * M_ + h * D_;
#pragma unroll
    for (int i = 0; i < 4; i++) {
        float inv = 1.0f / l[i];
        float4 v = make_float4(O[i][0] * inv, O[i][1] * inv, O[i][2] * inv, O[i][3] * inv);
        *(float4*)(&Z[zbase + (size_t)(rs + i) * M_ + cs]) = v;
    }
}

// ---------------------------------------------------------------------------
extern "C" void kernel_launch(void* const* d_in, const int* in_sizes, int n_in,
                              void* d_out, int out_size)
{
    const float* x      = (const float*)d_in[0];
    const float* W_attn = (const float*)d_in[1];
    const float* b_attn = (const float*)d_in[2];
    const float* W_proj = (const float*)d_in[3];
    const float* b_proj = (const float*)d_in[4];
    float* out = (float*)d_out;

    float *qkv, *z;
    cudaGetSymbolAddress((void**)&qkv, g_qkv);
    cudaGetSymbolAddress((void**)&z,   g_z);

    // 1) QKV projection: [4096,1024] @ [1024,3072] + b
    sgemm128<<<dim3(QKV_N / 128, NROWS / 128), 256>>>(x, W_attn, b_attn, qkv, QKV_N, M_);

    // 2) Causal flash attention
    cudaFuncSetAttribute(attn_kernel, cudaFuncAttributeMaxDynamicSharedMemorySize, SMEM_ATTN);
    attn_kernel<<<dim3(P_ / 64, H_, B_), 256, SMEM_ATTN>>>(qkv, z);

    // 3) Output projection: [4096,1024] @ [1024,1024] + b
    sgemm128<<<dim3(M_ / 128, NROWS / 128), 256>>>(z, W_proj, b_proj, out, M_, M_);
}

// round 7
// speedup vs baseline: 3.2772x; 3.2772x over previous
#include <cuda_runtime.h>
#include <stdint.h>

// Problem constants
#define B_   2
#define P_   2048
#define M_   1024
#define H_   16
#define D_   64
#define NROWS (B_ * P_)          // 4096
#define QKV_N (3 * M_)           // 3072

// Scratch (device globals: no allocations allowed)
__device__ __align__(128) float g_qkv[(size_t)NROWS * QKV_N];   // Q|K|V each [H,D]
__device__ __align__(128) float g_z  [(size_t)NROWS * M_];

// ---------------------------------------------------------------------------
// tf32 helpers
// ---------------------------------------------------------------------------
__device__ __forceinline__ uint32_t f2tf(float f) {
    uint32_t u;
    asm("cvt.rna.tf32.f32 %0, %1;" : "=r"(u) : "f"(f));
    return u;
}

// D += A(16x8) * B(8x8), tf32 inputs, fp32 accumulate.
__device__ __forceinline__ void mma_tf32(float* d, const uint32_t* a, const uint32_t* b) {
    asm volatile(
        "mma.sync.aligned.m16n8k8.row.col.f32.tf32.tf32.f32 "
        "{%0,%1,%2,%3}, {%4,%5,%6,%7}, {%8,%9}, {%0,%1,%2,%3};"
        : "+f"(d[0]), "+f"(d[1]), "+f"(d[2]), "+f"(d[3])
        : "r"(a[0]), "r"(a[1]), "r"(a[2]), "r"(a[3]), "r"(b[0]), "r"(b[1]));
}

// ---------------------------------------------------------------------------
// tf32 GEMM: C[rows,N] = A[rows,K] @ B[K,N] + bias
// CTA tile 128x128, BK=32, 8 warps (4 row x 2 col), warp tile 32x64.
// Smem stride 137 (== 9 mod 32): conflict-free transposed A stores, near-
// conflict-free fragment loads.
// ---------------------------------------------------------------------------
__global__ __launch_bounds__(256) void gemm_tf32(const float* __restrict__ A,
                                                 const float* __restrict__ Bm,
                                                 const float* __restrict__ bias,
                                                 float* __restrict__ C,
                                                 int N, int K)
{
    __shared__ uint32_t As[32][137];   // As[k][m]
    __shared__ uint32_t Bs[32][137];   // Bs[k][n]

    const int t = threadIdx.x, lane = t & 31, warp = t >> 5;
    const int wm = (warp & 3) * 32;    // warp row offset in tile
    const int wn = (warp >> 2) * 64;   // warp col offset in tile
    const int brow = blockIdx.y * 128, bcol = blockIdx.x * 128;
    const int qr = lane >> 2, qc = lane & 3;

    float acc[2][8][4];
#pragma unroll
    for (int mt = 0; mt < 2; mt++)
#pragma unroll
        for (int nt = 0; nt < 8; nt++)
#pragma unroll
            for (int j = 0; j < 4; j++) acc[mt][nt][j] = 0.0f;

    for (int k0 = 0; k0 < K; k0 += 32) {
        // A tile 128x32, gmem-coalesced float4 along k, transposed store
        for (int i = t; i < 1024; i += 256) {
            int row = i >> 3, kq = (i & 7) << 2;
            float4 v = *(const float4*)(A + (size_t)(brow + row) * K + k0 + kq);
            As[kq + 0][row] = f2tf(v.x);
            As[kq + 1][row] = f2tf(v.y);
            As[kq + 2][row] = f2tf(v.z);
            As[kq + 3][row] = f2tf(v.w);
        }
        // B tile 32x128
        for (int i = t; i < 1024; i += 256) {
            int kr = i >> 5, nq = (i & 31) << 2;
            float4 v = *(const float4*)(Bm + (size_t)(k0 + kr) * N + bcol + nq);
            Bs[kr][nq + 0] = f2tf(v.x);
            Bs[kr][nq + 1] = f2tf(v.y);
            Bs[kr][nq + 2] = f2tf(v.z);
            Bs[kr][nq + 3] = f2tf(v.w);
        }
        __syncthreads();

#pragma unroll
        for (int ks = 0; ks < 32; ks += 8) {
            uint32_t af[2][4], bf[8][2];
#pragma unroll
            for (int mt = 0; mt < 2; mt++) {
                int r = wm + mt * 16 + qr;
                af[mt][0] = As[ks + qc][r];
                af[mt][1] = As[ks + qc][r + 8];
                af[mt][2] = As[ks + qc + 4][r];
                af[mt][3] = As[ks + qc + 4][r + 8];
            }
#pragma unroll
            for (int nt = 0; nt < 8; nt++) {
                int c = wn + nt * 8 + qr;
                bf[nt][0] = Bs[ks + qc][c];
                bf[nt][1] = Bs[ks + qc + 4][c];
            }
#pragma unroll
            for (int mt = 0; mt < 2; mt++)
#pragma unroll
                for (int nt = 0; nt < 8; nt++)
                    mma_tf32(acc[mt][nt], af[mt], bf[nt]);
        }
        __syncthreads();
    }

    // Epilogue: fragment layout c0/c1 rows qr, c2/c3 rows qr+8; cols 2*qc,2*qc+1
#pragma unroll
    for (int mt = 0; mt < 2; mt++) {
        int r0 = brow + wm + mt * 16 + qr;
#pragma unroll
        for (int nt = 0; nt < 8; nt++) {
            int c0 = bcol + wn + nt * 8 + (qc << 1);
            float b0 = bias[c0], b1 = bias[c0 + 1];
            *(float2*)(C + (size_t)r0 * N + c0) =
                make_float2(acc[mt][nt][0] + b0, acc[mt][nt][1] + b1);
            *(float2*)(C + (size_t)(r0 + 8) * N + c0) =
                make_float2(acc[mt][nt][2] + b0, acc[mt][nt][3] + b1);
        }
    }
}

// ---------------------------------------------------------------------------
// Flash attention (causal) with tf32 tensor cores.
// CTA = (64-query tile, head, batch); 4 warps, each owns 16 query rows.
// S = Q K^T and O += P V both via m16n8k8. Smem stride 72 (== 8 mod 32):
// conflict-free for all four fragment access patterns.
// ---------------------------------------------------------------------------
#define AT_S 72
#define SMEM_ATTN (4 * 64 * AT_S * 4)   // Qs,Ks,Vs,Ps = 73728 B

__global__ __launch_bounds__(128) void attn_tf32(const float* __restrict__ qkv,
                                                 float* __restrict__ Z)
{
    extern __shared__ uint32_t sm4[];
    uint32_t* Qs = sm4;                  // [64][72]
    uint32_t* Ks = sm4 + 64 * AT_S;
    uint32_t* Vs = sm4 + 2 * 64 * AT_S;
    uint32_t* Ps = sm4 + 3 * 64 * AT_S;

    const int qt = blockIdx.x, h = blockIdx.y, b = blockIdx.z;
    const int t = threadIdx.x, lane = t & 31, warp = t >> 5;
    const int wrow = warp * 16;          // warp's query-row base within tile
    const int qr = lane >> 2, qc = lane & 3;

    const size_t rstride = QKV_N;
    const float* qbase = qkv + (size_t)(b * P_ + qt * 64) * rstride + h * D_;
    const float* kbase = qkv + (size_t)b * P_ * rstride + M_ + h * D_;
    const float* vbase = kbase + M_;

    // Load Q tile (scaled by 1/sqrt(D), converted to tf32)
    for (int i = t; i < 1024; i += 128) {
        int row = i >> 4, f4 = (i & 15) << 2;
        float4 v = *(const float4*)(qbase + (size_t)row * rstride + f4);
        Qs[row * AT_S + f4 + 0] = f2tf(v.x * 0.125f);
        Qs[row * AT_S + f4 + 1] = f2tf(v.y * 0.125f);
        Qs[row * AT_S + f4 + 2] = f2tf(v.z * 0.125f);
        Qs[row * AT_S + f4 + 3] = f2tf(v.w * 0.125f);
    }

    float m0 = -1e30f, m1 = -1e30f, l0 = 0.0f, l1 = 0.0f;
    float o[8][4];
#pragma unroll
    for (int nt = 0; nt < 8; nt++)
#pragma unroll
        for (int j = 0; j < 4; j++) o[nt][j] = 0.0f;

    for (int kb = 0; kb <= qt; kb++) {
        __syncthreads();   // prior-iter Ks/Vs reads done (also orders Q stores)
        for (int i = t; i < 1024; i += 128) {
            int row = i >> 4, f4 = (i & 15) << 2;
            size_t g = (size_t)(kb * 64 + row) * rstride + f4;
            float4 kv = *(const float4*)(kbase + g);
            float4 vv = *(const float4*)(vbase + g);
            Ks[row * AT_S + f4 + 0] = f2tf(kv.x);
            Ks[row * AT_S + f4 + 1] = f2tf(kv.y);
            Ks[row * AT_S + f4 + 2] = f2tf(kv.z);
            Ks[row * AT_S + f4 + 3] = f2tf(kv.w);
            Vs[row * AT_S + f4 + 0] = f2tf(vv.x);
            Vs[row * AT_S + f4 + 1] = f2tf(vv.y);
            Vs[row * AT_S + f4 + 2] = f2tf(vv.z);
            Vs[row * AT_S + f4 + 3] = f2tf(vv.w);
        }
        __syncthreads();

        // ---- S = Q K^T : warp computes 16x64, frags s[nt][4]
        float s[8][4];
#pragma unroll
        for (int nt = 0; nt < 8; nt++)
#pragma unroll
            for (int j = 0; j < 4; j++) s[nt][j] = 0.0f;

#pragma unroll
        for (int kt = 0; kt < 8; kt++) {
            uint32_t af[4], bf[8][2];
            af[0] = Qs[(wrow + qr) * AT_S + kt * 8 + qc];
            af[1] = Qs[(wrow + qr + 8) * AT_S + kt * 8 + qc];
            af[2] = Qs[(wrow + qr) * AT_S + kt * 8 + qc + 4];
            af[3] = Qs[(wrow + qr + 8) * AT_S + kt * 8 + qc + 4];
#pragma unroll
            for (int nt = 0; nt < 8; nt++) {
                bf[nt][0] = Ks[(nt * 8 + qr) * AT_S + kt * 8 + qc];
                bf[nt][1] = Ks[(nt * 8 + qr) * AT_S + kt * 8 + qc + 4];
            }
#pragma unroll
            for (int nt = 0; nt < 8; nt++) mma_tf32(s[nt], af, bf[nt]);
        }

        // ---- causal mask (diagonal tile only; row/col compare is tile-local)
        if (kb == qt) {
            int r0 = wrow + qr, r1 = r0 + 8;
#pragma unroll
            for (int nt = 0; nt < 8; nt++) {
                int c0 = nt * 8 + (qc << 1), c1 = c0 + 1;
                if (c0 > r0) s[nt][0] = -1e30f;
                if (c1 > r0) s[nt][1] = -1e30f;
                if (c0 > r1) s[nt][2] = -1e30f;
                if (c1 > r1) s[nt][3] = -1e30f;
            }
        }

        // ---- online softmax (rows qr and qr+8; reduce across quad lanes)
        float tm0 = -1e30f, tm1 = -1e30f;
#pragma unroll
        for (int nt = 0; nt < 8; nt++) {
            tm0 = fmaxf(tm0, fmaxf(s[nt][0], s[nt][1]));
            tm1 = fmaxf(tm1, fmaxf(s[nt][2], s[nt][3]));
        }
        tm0 = fmaxf(tm0, __shfl_xor_sync(0xffffffffu, tm0, 1));
        tm0 = fmaxf(tm0, __shfl_xor_sync(0xffffffffu, tm0, 2));
        tm1 = fmaxf(tm1, __shfl_xor_sync(0xffffffffu, tm1, 1));
        tm1 = fmaxf(tm1, __shfl_xor_sync(0xffffffffu, tm1, 2));

        float mn0 = fmaxf(m0, tm0), mn1 = fmaxf(m1, tm1);
        float sc0 = __expf(m0 - mn0), sc1 = __expf(m1 - mn1);
        float rs0 = 0.0f, rs1 = 0.0f;
#pragma unroll
        for (int nt = 0; nt < 8; nt++) {
            s[nt][0] = __expf(s[nt][0] - mn0);
            s[nt][1] = __expf(s[nt][1] - mn0);
            s[nt][2] = __expf(s[nt][2] - mn1);
            s[nt][3] = __expf(s[nt][3] - mn1);
            rs0 += s[nt][0] + s[nt][1];
            rs1 += s[nt][2] + s[nt][3];
        }
        rs0 += __shfl_xor_sync(0xffffffffu, rs0, 1);
        rs0 += __shfl_xor_sync(0xffffffffu, rs0, 2);
        rs1 += __shfl_xor_sync(0xffffffffu, rs1, 1);
        rs1 += __shfl_xor_sync(0xffffffffu, rs1, 2);
        l0 = l0 * sc0 + rs0;  l1 = l1 * sc1 + rs1;
        m0 = mn0;  m1 = mn1;
#pragma unroll
        for (int nt = 0; nt < 8; nt++) {
            o[nt][0] *= sc0;  o[nt][1] *= sc0;
            o[nt][2] *= sc1;  o[nt][3] *= sc1;
        }

        // ---- stage P (tf32) per-warp; only this warp reads its 16 rows back
#pragma unroll
        for (int nt = 0; nt < 8; nt++) {
            int c = nt * 8 + (qc << 1);
            Ps[(wrow + qr) * AT_S + c]     = f2tf(s[nt][0]);
            Ps[(wrow + qr) * AT_S + c + 1] = f2tf(s[nt][1]);
            Ps[(wrow + qr + 8) * AT_S + c]     = f2tf(s[nt][2]);
            Ps[(wrow + qr + 8) * AT_S + c + 1] = f2tf(s[nt][3]);
        }
        __syncwarp();

        // ---- O += P @ V
#pragma unroll
        for (int kt = 0; kt < 8; kt++) {
            uint32_t af[4], bf[8][2];
            af[0] = Ps[(wrow + qr) * AT_S + kt * 8 + qc];
            af[1] = Ps[(wrow + qr + 8) * AT_S + kt * 8 + qc];
            af[2] = Ps[(wrow + qr) * AT_S + kt * 8 + qc + 4];
            af[3] = Ps[(wrow + qr + 8) * AT_S + kt * 8 + qc + 4];
#pragma unroll
            for (int nt = 0; nt < 8; nt++) {
                bf[nt][0] = Vs[(kt * 8 + qc) * AT_S + nt * 8 + qr];
                bf[nt][1] = Vs[(kt * 8 + qc + 4) * AT_S + nt * 8 + qr];
            }
#pragma unroll
            for (int nt = 0; nt < 8; nt++) mma_tf32(o[nt], af, bf[nt]);
        }
    }

    // ---- normalize + store Z[b,p,h,d]
    float inv0 = 1.0f / l0, inv1 = 1.0f / l1;
    size_t zr0 = (size_t)(b * P_ + qt * 64 + wrow + qr) * M_ + h * D_;
    size_t zr1 = zr0 + (size_t)8 * M_;
#pragma unroll
    for (int nt = 0; nt < 8; nt++) {
        int c = nt * 8 + (qc << 1);
        *(float2*)(Z + zr0 + c) = make_float2(o[nt][0] * inv0, o[nt][1] * inv0);
        *(float2*)(Z + zr1 + c) = make_float2(o[nt][2] * inv1, o[nt][3] * inv1);
    }
}

// ---------------------------------------------------------------------------
extern "C" void kernel_launch(void* const* d_in, const int* in_sizes, int n_in,
                              void* d_out, int out_size)
{
    const float* x      = (const float*)d_in[0];
    const float* W_attn = (const float*)d_in[1];
    const float* b_attn = (const float*)d_in[2];
    const float* W_proj = (const float*)d_in[3];
    const float* b_proj = (const float*)d_in[4];
    float* out = (float*)d_out;

    float *qkv, *z;
    cudaGetSymbolAddress((void**)&qkv, g_qkv);
    cudaGetSymbolAddress((void**)&z,   g_z);

    // 1) QKV projection
    gemm_tf32<<<dim3(QKV_N / 128, NROWS / 128), 256>>>(x, W_attn, b_attn, qkv, QKV_N, M_);

    // 2) Causal flash attention (tf32 tensor cores)
    cudaFuncSetAttribute(attn_tf32, cudaFuncAttributeMaxDynamicSharedMemorySize, SMEM_ATTN);
    attn_tf32<<<dim3(P_ / 64, H_, B_), 128, SMEM_ATTN>>>(qkv, z);

    // 3) Output projection
    gemm_tf32<<<dim3(M_ / 128, NROWS / 128), 256>>>(z, W_proj, b_proj, out, M_, M_);
}

// round 8
// speedup vs baseline: 5.0963x; 1.5551x over previous
#include <cuda_runtime.h>
#include <stdint.h>

// Problem constants
#define B_   2
#define P_   2048
#define M_   1024
#define H_   16
#define D_   64
#define NROWS (B_ * P_)          // 4096
#define QKV_N (3 * M_)           // 3072

// Scratch (device globals: no allocations allowed)
__device__ __align__(128) float g_qkv[(size_t)NROWS * QKV_N];   // Q|K|V each [H,D]
__device__ __align__(128) float g_z  [(size_t)NROWS * M_];

// ---------------------------------------------------------------------------
// tf32 helpers
// ---------------------------------------------------------------------------
__device__ __forceinline__ uint32_t f2tf(float f) {
    uint32_t u;
    asm("cvt.rna.tf32.f32 %0, %1;" : "=r"(u) : "f"(f));
    return u;
}

// D += A(16x8) * B(8x8), tf32 inputs, fp32 accumulate.
__device__ __forceinline__ void mma_tf32(float* d, const uint32_t* a, const uint32_t* b) {
    asm volatile(
        "mma.sync.aligned.m16n8k8.row.col.f32.tf32.tf32.f32 "
        "{%0,%1,%2,%3}, {%4,%5,%6,%7}, {%8,%9}, {%0,%1,%2,%3};"
        : "+f"(d[0]), "+f"(d[1]), "+f"(d[2]), "+f"(d[3])
        : "r"(a[0]), "r"(a[1]), "r"(a[2]), "r"(a[3]), "r"(b[0]), "r"(b[1]));
}

__device__ __forceinline__ void cp_async16(void* smem_dst, const void* gmem_src) {
    uint32_t s = (uint32_t)__cvta_generic_to_shared(smem_dst);
    asm volatile("cp.async.cg.shared.global [%0], [%1], 16;" :: "r"(s), "l"(gmem_src));
}
__device__ __forceinline__ void cp_commit() { asm volatile("cp.async.commit_group;"); }
__device__ __forceinline__ void cp_wait1()  { asm volatile("cp.async.wait_group 1;" ::: "memory"); }

// ---------------------------------------------------------------------------
// tf32 GEMM, 3-stage cp.async pipeline.
// CTA tile 128x128, BK=32, 128 threads = 4 warps, warp tile 64x64.
// Smem natural layouts (cp.async): As[m][36] (pad->4*qr+qc banks distinct),
// Bs[k][136] (pad->8*qc+qr banks distinct). tf32 cvt at fragment-load time.
// ---------------------------------------------------------------------------
#define A_S   36                  // A row stride (floats): 32 k + 4 pad
#define B_S   136                 // B row stride (floats): 128 n + 8 pad
#define A_SZ  (128 * A_S)         // floats per A stage
#define B_SZ  (32 * B_S)          // floats per B stage
#define STG_SZ (A_SZ + B_SZ)
#define SMEM_GEMM (3 * STG_SZ * 4)   // 107520 B

__device__ __forceinline__ void gemm_load_stage(float* As, float* Bs,
                                                const float* __restrict__ A,
                                                const float* __restrict__ Bm,
                                                int brow, int bcol, int k0,
                                                int N, int K, int t)
{
#pragma unroll
    for (int j = 0; j < 8; j++) {               // A: 128x32, 8x16B per thread
        int i = t + 128 * j;
        int r = i >> 3, c = (i & 7) << 2;
        cp_async16(As + r * A_S + c, A + (size_t)(brow + r) * K + k0 + c);
    }
#pragma unroll
    for (int j = 0; j < 8; j++) {               // B: 32x128, 8x16B per thread
        int i = t + 128 * j;
        int r = i >> 5, c = (i & 31) << 2;
        cp_async16(Bs + r * B_S + c, Bm + (size_t)(k0 + r) * N + bcol + c);
    }
}

__global__ __launch_bounds__(128) void gemm_tf32(const float* __restrict__ A,
                                                 const float* __restrict__ Bm,
                                                 const float* __restrict__ bias,
                                                 float* __restrict__ C,
                                                 int N, int K)
{
    extern __shared__ float smg[];

    const int t = threadIdx.x, lane = t & 31, warp = t >> 5;
    const int wm = (warp >> 1) * 64;   // warp row offset in tile
    const int wn = (warp & 1) * 64;    // warp col offset in tile
    const int brow = blockIdx.y * 128, bcol = blockIdx.x * 128;
    const int qr = lane >> 2, qc = lane & 3;

    float acc[4][8][4];
#pragma unroll
    for (int mt = 0; mt < 4; mt++)
#pragma unroll
        for (int nt = 0; nt < 8; nt++)
#pragma unroll
            for (int j = 0; j < 4; j++) acc[mt][nt][j] = 0.0f;

    const int ntiles = K / 32;

    // Prologue: stages 0,1 in flight
    gemm_load_stage(smg, smg + A_SZ, A, Bm, brow, bcol, 0, N, K, t);
    cp_commit();
    gemm_load_stage(smg + STG_SZ, smg + STG_SZ + A_SZ, A, Bm, brow, bcol, 32, N, K, t);
    cp_commit();

    for (int kt = 0; kt < ntiles; kt++) {
        cp_wait1();            // oldest group (stage kt) complete
        __syncthreads();       // data visible to all warps; prior compute done

        int nxt = kt + 2;
        if (nxt < ntiles) {
            float* s = smg + (nxt % 3) * STG_SZ;
            gemm_load_stage(s, s + A_SZ, A, Bm, brow, bcol, nxt * 32, N, K, t);
        }
        cp_commit();           // unconditional: keeps group accounting uniform

        const float* Ac = smg + (kt % 3) * STG_SZ;
        const float* Bc = Ac + A_SZ;

#pragma unroll
        for (int ks = 0; ks < 32; ks += 8) {
            uint32_t af[4][4], bf[8][2];
#pragma unroll
            for (int mt = 0; mt < 4; mt++) {
                const float* ar = Ac + (wm + mt * 16 + qr) * A_S + ks;
                af[mt][0] = f2tf(ar[qc]);
                af[mt][1] = f2tf(ar[8 * A_S + qc]);
                af[mt][2] = f2tf(ar[qc + 4]);
                af[mt][3] = f2tf(ar[8 * A_S + qc + 4]);
            }
#pragma unroll
            for (int nt = 0; nt < 8; nt++) {
                int c = wn + nt * 8 + qr;
                bf[nt][0] = f2tf(Bc[(ks + qc) * B_S + c]);
                bf[nt][1] = f2tf(Bc[(ks + qc + 4) * B_S + c]);
            }
#pragma unroll
            for (int mt = 0; mt < 4; mt++)
#pragma unroll
                for (int nt = 0; nt < 8; nt++)
                    mma_tf32(acc[mt][nt], af[mt], bf[nt]);
        }
        __syncthreads();       // stage (kt)%3 free for reuse at kt+... (load into (kt+2)%3 next iter happens after top sync)
    }

    // Epilogue: c0/c1 rows qr, c2/c3 rows qr+8; cols 2*qc, 2*qc+1
#pragma unroll
    for (int mt = 0; mt < 4; mt++) {
        int r0 = brow + wm + mt * 16 + qr;
#pragma unroll
        for (int nt = 0; nt < 8; nt++) {
            int c0 = bcol + wn + nt * 8 + (qc << 1);
            float b0 = bias[c0], b1 = bias[c0 + 1];
            *(float2*)(C + (size_t)r0 * N + c0) =
                make_float2(acc[mt][nt][0] + b0, acc[mt][nt][1] + b1);
            *(float2*)(C + (size_t)(r0 + 8) * N + c0) =
                make_float2(acc[mt][nt][2] + b0, acc[mt][nt][3] + b1);
        }
    }
}

// ---------------------------------------------------------------------------
// Flash attention (causal) with tf32 tensor cores. (unchanged from R6 pass)
// CTA = (64-query tile, head, batch); 4 warps, each owns 16 query rows.
// Smem stride 72 (== 8 mod 32): conflict-free fragment access.
// ---------------------------------------------------------------------------
#define AT_S 72
#define SMEM_ATTN (4 * 64 * AT_S * 4)   // 73728 B

__global__ __launch_bounds__(128) void attn_tf32(const float* __restrict__ qkv,
                                                 float* __restrict__ Z)
{
    extern __shared__ uint32_t sm4[];
    uint32_t* Qs = sm4;                  // [64][72]
    uint32_t* Ks = sm4 + 64 * AT_S;
    uint32_t* Vs = sm4 + 2 * 64 * AT_S;
    uint32_t* Ps = sm4 + 3 * 64 * AT_S;

    const int qt = blockIdx.x, h = blockIdx.y, b = blockIdx.z;
    const int t = threadIdx.x, lane = t & 31, warp = t >> 5;
    const int wrow = warp * 16;
    const int qr = lane >> 2, qc = lane & 3;

    const size_t rstride = QKV_N;
    const float* qbase = qkv + (size_t)(b * P_ + qt * 64) * rstride + h * D_;
    const float* kbase = qkv + (size_t)b * P_ * rstride + M_ + h * D_;
    const float* vbase = kbase + M_;

    for (int i = t; i < 1024; i += 128) {
        int row = i >> 4, f4 = (i & 15) << 2;
        float4 v = *(const float4*)(qbase + (size_t)row * rstride + f4);
        Qs[row * AT_S + f4 + 0] = f2tf(v.x * 0.125f);
        Qs[row * AT_S + f4 + 1] = f2tf(v.y * 0.125f);
        Qs[row * AT_S + f4 + 2] = f2tf(v.z * 0.125f);
        Qs[row * AT_S + f4 + 3] = f2tf(v.w * 0.125f);
    }

    float m0 = -1e30f, m1 = -1e30f, l0 = 0.0f, l1 = 0.0f;
    float o[8][4];
#pragma unroll
    for (int nt = 0; nt < 8; nt++)
#pragma unroll
        for (int j = 0; j < 4; j++) o[nt][j] = 0.0f;

    for (int kb = 0; kb <= qt; kb++) {
        __syncthreads();
        for (int i = t; i < 1024; i += 128) {
            int row = i >> 4, f4 = (i & 15) << 2;
            size_t g = (size_t)(kb * 64 + row) * rstride + f4;
            float4 kv = *(const float4*)(kbase + g);
            float4 vv = *(const float4*)(vbase + g);
            Ks[row * AT_S + f4 + 0] = f2tf(kv.x);
            Ks[row * AT_S + f4 + 1] = f2tf(kv.y);
            Ks[row * AT_S + f4 + 2] = f2tf(kv.z);
            Ks[row * AT_S + f4 + 3] = f2tf(kv.w);
            Vs[row * AT_S + f4 + 0] = f2tf(vv.x);
            Vs[row * AT_S + f4 + 1] = f2tf(vv.y);
            Vs[row * AT_S + f4 + 2] = f2tf(vv.z);
            Vs[row * AT_S + f4 + 3] = f2tf(vv.w);
        }
        __syncthreads();

        float s[8][4];
#pragma unroll
        for (int nt = 0; nt < 8; nt++)
#pragma unroll
            for (int j = 0; j < 4; j++) s[nt][j] = 0.0f;

#pragma unroll
        for (int kt = 0; kt < 8; kt++) {
            uint32_t af[4], bf[8][2];
            af[0] = Qs[(wrow + qr) * AT_S + kt * 8 + qc];
            af[1] = Qs[(wrow + qr + 8) * AT_S + kt * 8 + qc];
            af[2] = Qs[(wrow + qr) * AT_S + kt * 8 + qc + 4];
            af[3] = Qs[(wrow + qr + 8) * AT_S + kt * 8 + qc + 4];
#pragma unroll
            for (int nt = 0; nt < 8; nt++) {
                bf[nt][0] = Ks[(nt * 8 + qr) * AT_S + kt * 8 + qc];
                bf[nt][1] = Ks[(nt * 8 + qr) * AT_S + kt * 8 + qc + 4];
            }
#pragma unroll
            for (int nt = 0; nt < 8; nt++) mma_tf32(s[nt], af, bf[nt]);
        }

        if (kb == qt) {
            int r0 = wrow + qr, r1 = r0 + 8;
#pragma unroll
            for (int nt = 0; nt < 8; nt++) {
                int c0 = nt * 8 + (qc << 1), c1 = c0 + 1;
                if (c0 > r0) s[nt][0] = -1e30f;
                if (c1 > r0) s[nt][1] = -1e30f;
                if (c0 > r1) s[nt][2] = -1e30f;
                if (c1 > r1) s[nt][3] = -1e30f;
            }
        }

        float tm0 = -1e30f, tm1 = -1e30f;
#pragma unroll
        for (int nt = 0; nt < 8; nt++) {
            tm0 = fmaxf(tm0, fmaxf(s[nt][0], s[nt][1]));
            tm1 = fmaxf(tm1, fmaxf(s[nt][2], s[nt][3]));
        }
        tm0 = fmaxf(tm0, __shfl_xor_sync(0xffffffffu, tm0, 1));
        tm0 = fmaxf(tm0, __shfl_xor_sync(0xffffffffu, tm0, 2));
        tm1 = fmaxf(tm1, __shfl_xor_sync(0xffffffffu, tm1, 1));
        tm1 = fmaxf(tm1, __shfl_xor_sync(0xffffffffu, tm1, 2));

        float mn0 = fmaxf(m0, tm0), mn1 = fmaxf(m1, tm1);
        float sc0 = __expf(m0 - mn0), sc1 = __expf(m1 - mn1);
        float rs0 = 0.0f, rs1 = 0.0f;
#pragma unroll
        for (int nt = 0; nt < 8; nt++) {
            s[nt][0] = __expf(s[nt][0] - mn0);
            s[nt][1] = __expf(s[nt][1] - mn0);
            s[nt][2] = __expf(s[nt][2] - mn1);
            s[nt][3] = __expf(s[nt][3] - mn1);
            rs0 += s[nt][0] + s[nt][1];
            rs1 += s[nt][2] + s[nt][3];
        }
        rs0 += __shfl_xor_sync(0xffffffffu, rs0, 1);
        rs0 += __shfl_xor_sync(0xffffffffu, rs0, 2);
        rs1 += __shfl_xor_sync(0xffffffffu, rs1, 1);
        rs1 += __shfl_xor_sync(0xffffffffu, rs1, 2);
        l0 = l0 * sc0 + rs0;  l1 = l1 * sc1 + rs1;
        m0 = mn0;  m1 = mn1;
#pragma unroll
        for (int nt = 0; nt < 8; nt++) {
            o[nt][0] *= sc0;  o[nt][1] *= sc0;
            o[nt][2] *= sc1;  o[nt][3] *= sc1;
        }

#pragma unroll
        for (int nt = 0; nt < 8; nt++) {
            int c = nt * 8 + (qc << 1);
            Ps[(wrow + qr) * AT_S + c]     = f2tf(s[nt][0]);
            Ps[(wrow + qr) * AT_S + c + 1] = f2tf(s[nt][1]);
            Ps[(wrow + qr + 8) * AT_S + c]     = f2tf(s[nt][2]);
            Ps[(wrow + qr + 8) * AT_S + c + 1] = f2tf(s[nt][3]);
        }
        __syncwarp();

#pragma unroll
        for (int kt = 0; kt < 8; kt++) {
            uint32_t af[4], bf[8][2];
            af[0] = Ps[(wrow + qr) * AT_S + kt * 8 + qc];
            af[1] = Ps[(wrow + qr + 8) * AT_S + kt * 8 + qc];
            af[2] = Ps[(wrow + qr) * AT_S + kt * 8 + qc + 4];
            af[3] = Ps[(wrow + qr + 8) * AT_S + kt * 8 + qc + 4];
#pragma unroll
            for (int nt = 0; nt < 8; nt++) {
                bf[nt][0] = Vs[(kt * 8 + qc) * AT_S + nt * 8 + qr];
                bf[nt][1] = Vs[(kt * 8 + qc + 4) * AT_S + nt * 8 + qr];
            }
#pragma unroll
            for (int nt = 0; nt < 8; nt++) mma_tf32(o[nt], af, bf[nt]);
        }
    }

    float inv0 = 1.0f / l0, inv1 = 1.0f / l1;
    size_t zr0 = (size_t)(b * P_ + qt * 64 + wrow + qr) * M_ + h * D_;
    size_t zr1 = zr0 + (size_t)8 * M_;
#pragma unroll
    for (int nt = 0; nt < 8; nt++) {
        int c = nt * 8 + (qc << 1);
        *(float2*)(Z + zr0 + c) = make_float2(o[nt][0] * inv0, o[nt][1] * inv0);
        *(float2*)(Z + zr1 + c) = make_float2(o[nt][2] * inv1, o[nt][3] * inv1);
    }
}

// ---------------------------------------------------------------------------
extern "C" void kernel_launch(void* const* d_in, const int* in_sizes, int n_in,
                              void* d_out, int out_size)
{
    const float* x      = (const float*)d_in[0];
    const float* W_attn = (const float*)d_in[1];
    const float* b_attn = (const float*)d_in[2];
    const float* W_proj = (const float*)d_in[3];
    const float* b_proj = (const float*)d_in[4];
    float* out = (float*)d_out;

    float *qkv, *z;
    cudaGetSymbolAddress((void**)&qkv, g_qkv);
    cudaGetSymbolAddress((void**)&z,   g_z);

    cudaFuncSetAttribute(gemm_tf32, cudaFuncAttributeMaxDynamicSharedMemorySize, SMEM_GEMM);
    cudaFuncSetAttribute(attn_tf32, cudaFuncAttributeMaxDynamicSharedMemorySize, SMEM_ATTN);

    // 1) QKV projection
    gemm_tf32<<<dim3(QKV_N / 128, NROWS / 128), 128, SMEM_GEMM>>>(x, W_attn, b_attn, qkv, QKV_N, M_);

    // 2) Causal flash attention
    attn_tf32<<<dim3(P_ / 64, H_, B_), 128, SMEM_ATTN>>>(qkv, z);

    // 3) Output projection
    gemm_tf32<<<dim3(M_ / 128, NROWS / 128), 128, SMEM_GEMM>>>(z, W_proj, b_proj, out, M_, M_);
}

// round 9
// speedup vs baseline: 5.4843x; 1.0761x over previous
#include <cuda_runtime.h>
#include <stdint.h>

// Problem constants
#define B_   2
#define P_   2048
#define M_   1024
#define H_   16
#define D_   64
#define NROWS (B_ * P_)          // 4096
#define QKV_N (3 * M_)           // 3072

// Scratch (device globals). All tf32-bit buffers are uint32.
__device__ __align__(128) uint32_t g_xt [(size_t)NROWS * M_];     // tf32(x)
__device__ __align__(128) uint32_t g_wa [(size_t)M_ * QKV_N];     // tf32(W_attn)
__device__ __align__(128) uint32_t g_wp [(size_t)M_ * M_];        // tf32(W_proj)
__device__ __align__(128) uint32_t g_qkv[(size_t)NROWS * QKV_N];  // tf32 Q|K|V
__device__ __align__(128) uint32_t g_z  [(size_t)NROWS * M_];     // tf32 attention out

// ---------------------------------------------------------------------------
// helpers
// ---------------------------------------------------------------------------
__device__ __forceinline__ uint32_t f2tf(float f) {
    uint32_t u;
    asm("cvt.rna.tf32.f32 %0, %1;" : "=r"(u) : "f"(f));
    return u;
}

__device__ __forceinline__ void mma_tf32(float* d, const uint32_t* a, const uint32_t* b) {
    asm volatile(
        "mma.sync.aligned.m16n8k8.row.col.f32.tf32.tf32.f32 "
        "{%0,%1,%2,%3}, {%4,%5,%6,%7}, {%8,%9}, {%0,%1,%2,%3};"
        : "+f"(d[0]), "+f"(d[1]), "+f"(d[2]), "+f"(d[3])
        : "r"(a[0]), "r"(a[1]), "r"(a[2]), "r"(a[3]), "r"(b[0]), "r"(b[1]));
}

__device__ __forceinline__ void cp_async16(void* smem_dst, const void* gmem_src) {
    uint32_t s = (uint32_t)__cvta_generic_to_shared(smem_dst);
    asm volatile("cp.async.cg.shared.global [%0], [%1], 16;" :: "r"(s), "l"(gmem_src));
}
__device__ __forceinline__ void cp_commit() { asm volatile("cp.async.commit_group;"); }
__device__ __forceinline__ void cp_wait1()  { asm volatile("cp.async.wait_group 1;" ::: "memory"); }

// ---------------------------------------------------------------------------
// Elementwise fp32 -> tf32-bits conversion (pre-pass, ~12 us total)
// ---------------------------------------------------------------------------
__global__ __launch_bounds__(256) void cvt_tf32_kernel(const float4* __restrict__ in,
                                                       uint4* __restrict__ out, int n4)
{
    int i = blockIdx.x * blockDim.x + threadIdx.x;
    if (i < n4) {
        float4 v = in[i];
        out[i] = make_uint4(f2tf(v.x), f2tf(v.y), f2tf(v.z), f2tf(v.w));
    }
}

// ---------------------------------------------------------------------------
// tf32 GEMM, 3-stage cp.async pipeline, cvt-free mainloop.
// Inputs A,B are tf32 bits. CTA tile 128x128, BK=32, 128 threads, warp 64x64.
// OUT_TF32: epilogue stores tf32 bits (for qkv) vs fp32 (final output).
// ---------------------------------------------------------------------------
#define A_S   36
#define B_S   136
#define A_SZ  (128 * A_S)
#define B_SZ  (32 * B_S)
#define STG_SZ (A_SZ + B_SZ)
#define SMEM_GEMM (3 * STG_SZ * 4)   // 107520 B

__device__ __forceinline__ void gemm_load_stage(uint32_t* As, uint32_t* Bs,
                                                const uint32_t* __restrict__ A,
                                                const uint32_t* __restrict__ Bm,
                                                int brow, int bcol, int k0,
                                                int N, int K, int t)
{
#pragma unroll
    for (int j = 0; j < 8; j++) {
        int i = t + 128 * j;
        int r = i >> 3, c = (i & 7) << 2;
        cp_async16(As + r * A_S + c, A + (size_t)(brow + r) * K + k0 + c);
    }
#pragma unroll
    for (int j = 0; j < 8; j++) {
        int i = t + 128 * j;
        int r = i >> 5, c = (i & 31) << 2;
        cp_async16(Bs + r * B_S + c, Bm + (size_t)(k0 + r) * N + bcol + c);
    }
}

template <bool OUT_TF32>
__global__ __launch_bounds__(128) void gemm_tf32(const uint32_t* __restrict__ A,
                                                 const uint32_t* __restrict__ Bm,
                                                 const float* __restrict__ bias,
                                                 void* __restrict__ Cv,
                                                 int N, int K)
{
    extern __shared__ uint32_t smg[];

    const int t = threadIdx.x, lane = t & 31, warp = t >> 5;
    const int wm = (warp >> 1) * 64;
    const int wn = (warp & 1) * 64;
    const int brow = blockIdx.y * 128, bcol = blockIdx.x * 128;
    const int qr = lane >> 2, qc = lane & 3;

    float acc[4][8][4];
#pragma unroll
    for (int mt = 0; mt < 4; mt++)
#pragma unroll
        for (int nt = 0; nt < 8; nt++)
#pragma unroll
            for (int j = 0; j < 4; j++) acc[mt][nt][j] = 0.0f;

    const int ntiles = K / 32;

    gemm_load_stage(smg, smg + A_SZ, A, Bm, brow, bcol, 0, N, K, t);
    cp_commit();
    gemm_load_stage(smg + STG_SZ, smg + STG_SZ + A_SZ, A, Bm, brow, bcol, 32, N, K, t);
    cp_commit();

    for (int kt = 0; kt < ntiles; kt++) {
        cp_wait1();
        __syncthreads();

        int nxt = kt + 2;
        if (nxt < ntiles) {
            uint32_t* s = smg + (nxt % 3) * STG_SZ;
            gemm_load_stage(s, s + A_SZ, A, Bm, brow, bcol, nxt * 32, N, K, t);
        }
        cp_commit();

        const uint32_t* Ac = smg + (kt % 3) * STG_SZ;
        const uint32_t* Bc = Ac + A_SZ;

#pragma unroll
        for (int ks = 0; ks < 32; ks += 8) {
            uint32_t af[4][4], bf[8][2];
#pragma unroll
            for (int mt = 0; mt < 4; mt++) {
                const uint32_t* ar = Ac + (wm + mt * 16 + qr) * A_S + ks;
                af[mt][0] = ar[qc];
                af[mt][1] = ar[8 * A_S + qc];
                af[mt][2] = ar[qc + 4];
                af[mt][3] = ar[8 * A_S + qc + 4];
            }
#pragma unroll
            for (int nt = 0; nt < 8; nt++) {
                int c = wn + nt * 8 + qr;
                bf[nt][0] = Bc[(ks + qc) * B_S + c];
                bf[nt][1] = Bc[(ks + qc + 4) * B_S + c];
            }
#pragma unroll
            for (int mt = 0; mt < 4; mt++)
#pragma unroll
                for (int nt = 0; nt < 8; nt++)
                    mma_tf32(acc[mt][nt], af[mt], bf[nt]);
        }
        __syncthreads();
    }

#pragma unroll
    for (int mt = 0; mt < 4; mt++) {
        int r0 = brow + wm + mt * 16 + qr;
#pragma unroll
        for (int nt = 0; nt < 8; nt++) {
            int c0 = bcol + wn + nt * 8 + (qc << 1);
            float b0 = bias[c0], b1 = bias[c0 + 1];
            float v00 = acc[mt][nt][0] + b0, v01 = acc[mt][nt][1] + b1;
            float v10 = acc[mt][nt][2] + b0, v11 = acc[mt][nt][3] + b1;
            if (OUT_TF32) {
                uint32_t* C = (uint32_t*)Cv;
                *(uint2*)(C + (size_t)r0 * N + c0)       = make_uint2(f2tf(v00), f2tf(v01));
                *(uint2*)(C + (size_t)(r0 + 8) * N + c0) = make_uint2(f2tf(v10), f2tf(v11));
            } else {
                float* C = (float*)Cv;
                *(float2*)(C + (size_t)r0 * N + c0)       = make_float2(v00, v01);
                *(float2*)(C + (size_t)(r0 + 8) * N + c0) = make_float2(v10, v11);
            }
        }
    }
}

// ---------------------------------------------------------------------------
// Flash attention (causal), tf32 tensor cores, cvt-free K/V path.
// qkv and Z are tf32 bits. K/V staged via cp.async with 2-stage double buffer.
// CTA = (64-query tile, head, batch); 4 warps; smem stride 72.
// ---------------------------------------------------------------------------
#define AT_S 72
#define AT_T (64 * AT_S)                 // 4608 words per tile
#define SMEM_ATTN ((2 * AT_T + 2 * 2 * AT_T) * 4)   // Qs+Ps + 2x(Ks+Vs) = 110592 B

__global__ __launch_bounds__(128) void attn_tf32(const uint32_t* __restrict__ qkv,
                                                 uint32_t* __restrict__ Z)
{
    extern __shared__ uint32_t sm4[];
    uint32_t* Qs = sm4;                  // [64][72]
    uint32_t* Ps = sm4 + AT_T;
    uint32_t* KV = sm4 + 2 * AT_T;       // buf b: Ks at b*2*AT_T, Vs at b*2*AT_T + AT_T

    const int qt = blockIdx.x, h = blockIdx.y, b = blockIdx.z;
    const int t = threadIdx.x, lane = t & 31, warp = t >> 5;
    const int wrow = warp * 16;
    const int qr = lane >> 2, qc = lane & 3;

    const size_t rstride = QKV_N;
    const uint32_t* qbase = qkv + (size_t)(b * P_ + qt * 64) * rstride + h * D_;
    const uint32_t* kbase = qkv + (size_t)b * P_ * rstride + M_ + h * D_;
    const uint32_t* vbase = kbase + M_;

    // Q tile: tf32 bits scaled by 1/8 (exponent-only, exact on tf32)
    for (int i = t; i < 1024; i += 128) {
        int row = i >> 4, f4 = (i & 15) << 2;
        const uint32_t* src = qbase + (size_t)row * rstride + f4;
        uint4 u = *(const uint4*)src;
        float4 v = make_float4(__uint_as_float(u.x) * 0.125f, __uint_as_float(u.y) * 0.125f,
                               __uint_as_float(u.z) * 0.125f, __uint_as_float(u.w) * 0.125f);
        *(uint4*)(&Qs[row * AT_S + f4]) = make_uint4(__float_as_uint(v.x), __float_as_uint(v.y),
                                                     __float_as_uint(v.z), __float_as_uint(v.w));
    }

    // Prefetch kb=0 into buffer 0
    {
        uint32_t* Ks = KV;
        uint32_t* Vs = KV + AT_T;
#pragma unroll
        for (int j = 0; j < 8; j++) {
            int i = t + 128 * j;
            int row = i >> 4, f4 = (i & 15) << 2;
            size_t g = (size_t)row * rstride + f4;
            cp_async16(Ks + row * AT_S + f4, kbase + g);
            cp_async16(Vs + row * AT_S + f4, vbase + g);
        }
        cp_commit();
    }

    float m0 = -1e30f, m1 = -1e30f, l0 = 0.0f, l1 = 0.0f;
    float o[8][4];
#pragma unroll
    for (int nt = 0; nt < 8; nt++)
#pragma unroll
        for (int j = 0; j < 4; j++) o[nt][j] = 0.0f;

    for (int kb = 0; kb <= qt; kb++) {
        __syncthreads();   // all warps done reading the buffer we're about to overwrite
        if (kb + 1 <= qt) {
            uint32_t* Ks = KV + ((kb + 1) & 1) * 2 * AT_T;
            uint32_t* Vs = Ks + AT_T;
#pragma unroll
            for (int j = 0; j < 8; j++) {
                int i = t + 128 * j;
                int row = i >> 4, f4 = (i & 15) << 2;
                size_t g = (size_t)((kb + 1) * 64 + row) * rstride + f4;
                cp_async16(Ks + row * AT_S + f4, kbase + g);
                cp_async16(Vs + row * AT_S + f4, vbase + g);
            }
        }
        cp_commit();
        cp_wait1();        // group kb complete (kb+1 still in flight)
        __syncthreads();   // cross-thread visibility of completed tile

        const uint32_t* Ks = KV + (kb & 1) * 2 * AT_T;
        const uint32_t* Vs = Ks + AT_T;

        // ---- S = Q K^T
        float s[8][4];
#pragma unroll
        for (int nt = 0; nt < 8; nt++)
#pragma unroll
            for (int j = 0; j < 4; j++) s[nt][j] = 0.0f;

#pragma unroll
        for (int kt = 0; kt < 8; kt++) {
            uint32_t af[4], bf[8][2];
            af[0] = Qs[(wrow + qr) * AT_S + kt * 8 + qc];
            af[1] = Qs[(wrow + qr + 8) * AT_S + kt * 8 + qc];
            af[2] = Qs[(wrow + qr) * AT_S + kt * 8 + qc + 4];
            af[3] = Qs[(wrow + qr + 8) * AT_S + kt * 8 + qc + 4];
#pragma unroll
            for (int nt = 0; nt < 8; nt++) {
                bf[nt][0] = Ks[(nt * 8 + qr) * AT_S + kt * 8 + qc];
                bf[nt][1] = Ks[(nt * 8 + qr) * AT_S + kt * 8 + qc + 4];
            }
#pragma unroll
            for (int nt = 0; nt < 8; nt++) mma_tf32(s[nt], af, bf[nt]);
        }

        if (kb == qt) {
            int r0 = wrow + qr, r1 = r0 + 8;
#pragma unroll
            for (int nt = 0; nt < 8; nt++) {
                int c0 = nt * 8 + (qc << 1), c1 = c0 + 1;
                if (c0 > r0) s[nt][0] = -1e30f;
                if (c1 > r0) s[nt][1] = -1e30f;
                if (c0 > r1) s[nt][2] = -1e30f;
                if (c1 > r1) s[nt][3] = -1e30f;
            }
        }

        // ---- online softmax
        float tm0 = -1e30f, tm1 = -1e30f;
#pragma unroll
        for (int nt = 0; nt < 8; nt++) {
            tm0 = fmaxf(tm0, fmaxf(s[nt][0], s[nt][1]));
            tm1 = fmaxf(tm1, fmaxf(s[nt][2], s[nt][3]));
        }
        tm0 = fmaxf(tm0, __shfl_xor_sync(0xffffffffu, tm0, 1));
        tm0 = fmaxf(tm0, __shfl_xor_sync(0xffffffffu, tm0, 2));
        tm1 = fmaxf(tm1, __shfl_xor_sync(0xffffffffu, tm1, 1));
        tm1 = fmaxf(tm1, __shfl_xor_sync(0xffffffffu, tm1, 2));

        float mn0 = fmaxf(m0, tm0), mn1 = fmaxf(m1, tm1);
        float sc0 = __expf(m0 - mn0), sc1 = __expf(m1 - mn1);
        float rs0 = 0.0f, rs1 = 0.0f;
#pragma unroll
        for (int nt = 0; nt < 8; nt++) {
            s[nt][0] = __expf(s[nt][0] - mn0);
            s[nt][1] = __expf(s[nt][1] - mn0);
            s[nt][2] = __expf(s[nt][2] - mn1);
            s[nt][3] = __expf(s[nt][3] - mn1);
            rs0 += s[nt][0] + s[nt][1];
            rs1 += s[nt][2] + s[nt][3];
        }
        rs0 += __shfl_xor_sync(0xffffffffu, rs0, 1);
        rs0 += __shfl_xor_sync(0xffffffffu, rs0, 2);
        rs1 += __shfl_xor_sync(0xffffffffu, rs1, 1);
        rs1 += __shfl_xor_sync(0xffffffffu, rs1, 2);
        l0 = l0 * sc0 + rs0;  l1 = l1 * sc1 + rs1;
        m0 = mn0;  m1 = mn1;
#pragma unroll
        for (int nt = 0; nt < 8; nt++) {
            o[nt][0] *= sc0;  o[nt][1] *= sc0;
            o[nt][2] *= sc1;  o[nt][3] *= sc1;
        }

        // ---- stage P (tf32), per-warp rows only
#pragma unroll
        for (int nt = 0; nt < 8; nt++) {
            int c = nt * 8 + (qc << 1);
            Ps[(wrow + qr) * AT_S + c]         = f2tf(s[nt][0]);
            Ps[(wrow + qr) * AT_S + c + 1]     = f2tf(s[nt][1]);
            Ps[(wrow + qr + 8) * AT_S + c]     = f2tf(s[nt][2]);
            Ps[(wrow + qr + 8) * AT_S + c + 1] = f2tf(s[nt][3]);
        }
        __syncwarp();

        // ---- O += P @ V
#pragma unroll
        for (int kt = 0; kt < 8; kt++) {
            uint32_t af[4], bf[8][2];
            af[0] = Ps[(wrow + qr) * AT_S + kt * 8 + qc];
            af[1] = Ps[(wrow + qr + 8) * AT_S + kt * 8 + qc];
            af[2] = Ps[(wrow + qr) * AT_S + kt * 8 + qc + 4];
            af[3] = Ps[(wrow + qr + 8) * AT_S + kt * 8 + qc + 4];
#pragma unroll
            for (int nt = 0; nt < 8; nt++) {
                bf[nt][0] = Vs[(kt * 8 + qc) * AT_S + nt * 8 + qr];
                bf[nt][1] = Vs[(kt * 8 + qc + 4) * AT_S + nt * 8 + qr];
            }
#pragma unroll
            for (int nt = 0; nt < 8; nt++) mma_tf32(o[nt], af, bf[nt]);
        }
    }

    // ---- normalize + store Z (tf32 bits)
    float inv0 = 1.0f / l0, inv1 = 1.0f / l1;
    size_t zr0 = (size_t)(b * P_ + qt * 64 + wrow + qr) * M_ + h * D_;
    size_t zr1 = zr0 + (size_t)8 * M_;
#pragma unroll
    for (int nt = 0; nt < 8; nt++) {
        int c = nt * 8 + (qc << 1);
        *(uint2*)(Z + zr0 + c) = make_uint2(f2tf(o[nt][0] * inv0), f2tf(o[nt][1] * inv0));
        *(uint2*)(Z + zr1 + c) = make_uint2(f2tf(o[nt][2] * inv1), f2tf(o[nt][3] * inv1));
    }
}

// ---------------------------------------------------------------------------
extern "C" void kernel_launch(void* const* d_in, const int* in_sizes, int n_in,
                              void* d_out, int out_size)
{
    const float* x      = (const float*)d_in[0];
    const float* W_attn = (const float*)d_in[1];
    const float* b_attn = (const float*)d_in[2];
    const float* W_proj = (const float*)d_in[3];
    const float* b_proj = (const float*)d_in[4];

    uint32_t *xt, *wa, *wp, *qkv, *z;
    cudaGetSymbolAddress((void**)&xt,  g_xt);
    cudaGetSymbolAddress((void**)&wa,  g_wa);
    cudaGetSymbolAddress((void**)&wp,  g_wp);
    cudaGetSymbolAddress((void**)&qkv, g_qkv);
    cudaGetSymbolAddress((void**)&z,   g_z);

    cudaFuncSetAttribute(gemm_tf32<true>,  cudaFuncAttributeMaxDynamicSharedMemorySize, SMEM_GEMM);
    cudaFuncSetAttribute(gemm_tf32<false>, cudaFuncAttributeMaxDynamicSharedMemorySize, SMEM_GEMM);
    cudaFuncSetAttribute(attn_tf32, cudaFuncAttributeMaxDynamicSharedMemorySize, SMEM_ATTN);

    // 0) pre-convert inputs to tf32 bits
    {
        int n4x = NROWS * M_ / 4, n4a = M_ * QKV_N / 4, n4p = M_ * M_ / 4;
        cvt_tf32_kernel<<<(n4x + 255) / 256, 256>>>((const float4*)x, (uint4*)xt, n4x);
        cvt_tf32_kernel<<<(n4a + 255) / 256, 256>>>((const float4*)W_attn, (uint4*)wa, n4a);
        cvt_tf32_kernel<<<(n4p + 255) / 256, 256>>>((const float4*)W_proj, (uint4*)wp, n4p);
    }

    // 1) QKV projection (tf32 out)
    gemm_tf32<true><<<dim3(QKV_N / 128, NROWS / 128), 128, SMEM_GEMM>>>(xt, wa, b_attn, qkv, QKV_N, M_);

    // 2) Causal flash attention (tf32 in/out)
    attn_tf32<<<dim3(P_ / 64, H_, B_), 128, SMEM_ATTN>>>(qkv, z);

    // 3) Output projection (fp32 out)
    gemm_tf32<false><<<dim3(M_ / 128, NROWS / 128), 128, SMEM_GEMM>>>(z, wp, b_proj, (float*)d_out, M_, M_);
}

// round 12
// speedup vs baseline: 5.5027x; 1.0034x over previous
#include <cuda_runtime.h>
#include <stdint.h>

// Problem constants
#define B_   2
#define P_   2048
#define M_   1024
#define H_   16
#define D_   64
#define NROWS (B_ * P_)          // 4096
#define QKV_N (3 * M_)           // 3072

// Scratch (device globals). All tf32-bit buffers are uint32.
__device__ __align__(128) uint32_t g_xt [(size_t)NROWS * M_];     // tf32(x)
__device__ __align__(128) uint32_t g_wa [(size_t)M_ * QKV_N];     // tf32(W_attn) [K][N]
__device__ __align__(128) uint32_t g_wp [(size_t)M_ * M_];        // tf32(W_proj) [K][N]
__device__ __align__(128) uint32_t g_qkv[(size_t)NROWS * QKV_N];  // tf32 Q|K|V
__device__ __align__(128) uint32_t g_z  [(size_t)NROWS * M_];     // tf32 attention out

// ---------------------------------------------------------------------------
// helpers
// ---------------------------------------------------------------------------
__device__ __forceinline__ uint32_t f2tf(float f) {
    uint32_t u;
    asm("cvt.rna.tf32.f32 %0, %1;" : "=r"(u) : "f"(f));
    return u;
}

__device__ __forceinline__ void mma_tf32(float* d, const uint32_t* a, const uint32_t* b) {
    asm volatile(
        "mma.sync.aligned.m16n8k8.row.col.f32.tf32.tf32.f32 "
        "{%0,%1,%2,%3}, {%4,%5,%6,%7}, {%8,%9}, {%0,%1,%2,%3};"
        : "+f"(d[0]), "+f"(d[1]), "+f"(d[2]), "+f"(d[3])
        : "r"(a[0]), "r"(a[1]), "r"(a[2]), "r"(a[3]), "r"(b[0]), "r"(b[1]));
}

__device__ __forceinline__ void cp_async16(void* smem_dst, const void* gmem_src) {
    uint32_t s = (uint32_t)__cvta_generic_to_shared(smem_dst);
    asm volatile("cp.async.cg.shared.global [%0], [%1], 16;" :: "r"(s), "l"(gmem_src));
}
__device__ __forceinline__ void cp_commit() { asm volatile("cp.async.commit_group;"); }
__device__ __forceinline__ void cp_wait1()  { asm volatile("cp.async.wait_group 1;" ::: "memory"); }

// ---------------------------------------------------------------------------
// Elementwise fp32 -> tf32-bits conversion (pre-pass)
// ---------------------------------------------------------------------------
__global__ __launch_bounds__(256) void cvt_tf32_kernel(const float4* __restrict__ in,
                                                       uint4* __restrict__ out, int n4)
{
    int i = blockIdx.x * blockDim.x + threadIdx.x;
    if (i < n4) {
        float4 v = in[i];
        out[i] = make_uint4(f2tf(v.x), f2tf(v.y), f2tf(v.z), f2tf(v.w));
    }
}

// ---------------------------------------------------------------------------
// tf32 GEMM, 3-stage cp.async pipeline, cvt-free mainloop.
// CTA tile 128x128, BK=32, 256 threads = 8 warps (2 row x 4 col),
// warp tile 64x32 -> acc 64 regs/thread -> 2 CTAs/SM = 16 warps/SM.
// Smem: As[m][36] (4*qr+qc banks distinct), Bs[k][136] (8*qc+qr distinct).
// ---------------------------------------------------------------------------
#define A_S   36
#define B_S   136
#define A_SZ  (128 * A_S)
#define B_SZ  (32 * B_S)
#define STG_SZ (A_SZ + B_SZ)
#define SMEM_GEMM (3 * STG_SZ * 4)   // 107520 B

__device__ __forceinline__ void gemm_load_stage(uint32_t* As, uint32_t* Bs,
                                                const uint32_t* __restrict__ A,
                                                const uint32_t* __restrict__ Bm,
                                                int brow, int bcol, int k0,
                                                int N, int K, int t)
{
#pragma unroll
    for (int j = 0; j < 4; j++) {               // A: 128x32, 4x16B per thread
        int i = t + 256 * j;
        int r = i >> 3, c = (i & 7) << 2;
        cp_async16(As + r * A_S + c, A + (size_t)(brow + r) * K + k0 + c);
    }
#pragma unroll
    for (int j = 0; j < 4; j++) {               // B: 32x128, 4x16B per thread
        int i = t + 256 * j;
        int r = i >> 5, c = (i & 31) << 2;
        cp_async16(Bs + r * B_S + c, Bm + (size_t)(k0 + r) * N + bcol + c);
    }
}

template <bool OUT_TF32>
__global__ __launch_bounds__(256, 2) void gemm_tf32(const uint32_t* __restrict__ A,
                                                    const uint32_t* __restrict__ Bm,
                                                    const float* __restrict__ bias,
                                                    void* __restrict__ Cv,
                                                    int N, int K)
{
    extern __shared__ uint32_t smg[];

    const int t = threadIdx.x, lane = t & 31, warp = t >> 5;
    const int wm = (warp >> 2) * 64;   // 2 warp-row groups of 64
    const int wn = (warp & 3) * 32;    // 4 warp-col groups of 32
    const int brow = blockIdx.y * 128, bcol = blockIdx.x * 128;
    const int qr = lane >> 2, qc = lane & 3;

    float acc[4][4][4];
#pragma unroll
    for (int mt = 0; mt < 4; mt++)
#pragma unroll
        for (int nt = 0; nt < 4; nt++)
#pragma unroll
            for (int j = 0; j < 4; j++) acc[mt][nt][j] = 0.0f;

    const int ntiles = K / 32;

    gemm_load_stage(smg, smg + A_SZ, A, Bm, brow, bcol, 0, N, K, t);
    cp_commit();
    gemm_load_stage(smg + STG_SZ, smg + STG_SZ + A_SZ, A, Bm, brow, bcol, 32, N, K, t);
    cp_commit();

    for (int kt = 0; kt < ntiles; kt++) {
        cp_wait1();
        __syncthreads();

        int nxt = kt + 2;
        if (nxt < ntiles) {
            uint32_t* s = smg + (nxt % 3) * STG_SZ;
            gemm_load_stage(s, s + A_SZ, A, Bm, brow, bcol, nxt * 32, N, K, t);
        }
        cp_commit();

        const uint32_t* Ac = smg + (kt % 3) * STG_SZ;
        const uint32_t* Bc = Ac + A_SZ;

#pragma unroll
        for (int ks = 0; ks < 32; ks += 8) {
            uint32_t af[4][4], bf[4][2];
#pragma unroll
            for (int mt = 0; mt < 4; mt++) {
                const uint32_t* ar = Ac + (wm + mt * 16 + qr) * A_S + ks;
                af[mt][0] = ar[qc];
                af[mt][1] = ar[8 * A_S + qc];
                af[mt][2] = ar[qc + 4];
                af[mt][3] = ar[8 * A_S + qc + 4];
            }
#pragma unroll
            for (int nt = 0; nt < 4; nt++) {
                int c = wn + nt * 8 + qr;
                bf[nt][0] = Bc[(ks + qc) * B_S + c];
                bf[nt][1] = Bc[(ks + qc + 4) * B_S + c];
            }
#pragma unroll
            for (int mt = 0; mt < 4; mt++)
#pragma unroll
                for (int nt = 0; nt < 4; nt++)
                    mma_tf32(acc[mt][nt], af[mt], bf[nt]);
        }
        __syncthreads();
    }

    // Epilogue: c0/c1 rows qr, c2/c3 rows qr+8; cols 2*qc, 2*qc+1
#pragma unroll
    for (int mt = 0; mt < 4; mt++) {
        int r0 = brow + wm + mt * 16 + qr;
#pragma unroll
        for (int nt = 0; nt < 4; nt++) {
            int c0 = bcol + wn + nt * 8 + (qc << 1);
            float b0 = bias[c0], b1 = bias[c0 + 1];
            float v00 = acc[mt][nt][0] + b0, v01 = acc[mt][nt][1] + b1;
            float v10 = acc[mt][nt][2] + b0, v11 = acc[mt][nt][3] + b1;
            if (OUT_TF32) {
                uint32_t* C = (uint32_t*)Cv;
                *(uint2*)(C + (size_t)r0 * N + c0)       = make_uint2(f2tf(v00), f2tf(v01));
                *(uint2*)(C + (size_t)(r0 + 8) * N + c0) = make_uint2(f2tf(v10), f2tf(v11));
            } else {
                float* C = (float*)Cv;
                *(float2*)(C + (size_t)r0 * N + c0)       = make_float2(v00, v01);
                *(float2*)(C + (size_t)(r0 + 8) * N + c0) = make_float2(v10, v11);
            }
        }
    }
}

// ---------------------------------------------------------------------------
// Flash attention (causal), tf32 warp mma, cp.async K/V double buffer.
// (unchanged from R8 passing version)
// ---------------------------------------------------------------------------
#define AT_S 72
#define AT_T (64 * AT_S)
#define SMEM_ATTN ((2 * AT_T + 2 * 2 * AT_T) * 4)   // 110592 B

__global__ __launch_bounds__(128) void attn_tf32(const uint32_t* __restrict__ qkv,
                                                 uint32_t* __restrict__ Z)
{
    extern __shared__ uint32_t sm4[];
    uint32_t* Qs = sm4;
    uint32_t* Ps = sm4 + AT_T;
    uint32_t* KV = sm4 + 2 * AT_T;

    const int qt = blockIdx.x, h = blockIdx.y, b = blockIdx.z;
    const int t = threadIdx.x, lane = t & 31, warp = t >> 5;
    const int wrow = warp * 16;
    const int qr = lane >> 2, qc = lane & 3;

    const size_t rstride = QKV_N;
    const uint32_t* qbase = qkv + (size_t)(b * P_ + qt * 64) * rstride + h * D_;
    const uint32_t* kbase = qkv + (size_t)b * P_ * rstride + M_ + h * D_;
    const uint32_t* vbase = kbase + M_;

    for (int i = t; i < 1024; i += 128) {
        int row = i >> 4, f4 = (i & 15) << 2;
        uint4 u = *(const uint4*)(qbase + (size_t)row * rstride + f4);
        float4 v = make_float4(__uint_as_float(u.x) * 0.125f, __uint_as_float(u.y) * 0.125f,
                               __uint_as_float(u.z) * 0.125f, __uint_as_float(u.w) * 0.125f);
        *(uint4*)(&Qs[row * AT_S + f4]) = make_uint4(__float_as_uint(v.x), __float_as_uint(v.y),
                                                     __float_as_uint(v.z), __float_as_uint(v.w));
    }

    {
        uint32_t* Ks = KV;
        uint32_t* Vs = KV + AT_T;
#pragma unroll
        for (int j = 0; j < 8; j++) {
            int i = t + 128 * j;
            int row = i >> 4, f4 = (i & 15) << 2;
            size_t g = (size_t)row * rstride + f4;
            cp_async16(Ks + row * AT_S + f4, kbase + g);
            cp_async16(Vs + row * AT_S + f4, vbase + g);
        }
        cp_commit();
    }

    float m0 = -1e30f, m1 = -1e30f, l0 = 0.0f, l1 = 0.0f;
    float o[8][4];
#pragma unroll
    for (int nt = 0; nt < 8; nt++)
#pragma unroll
        for (int j = 0; j < 4; j++) o[nt][j] = 0.0f;

    for (int kb = 0; kb <= qt; kb++) {
        __syncthreads();
        if (kb + 1 <= qt) {
            uint32_t* Ks = KV + ((kb + 1) & 1) * 2 * AT_T;
            uint32_t* Vs = Ks + AT_T;
#pragma unroll
            for (int j = 0; j < 8; j++) {
                int i = t + 128 * j;
                int row = i >> 4, f4 = (i & 15) << 2;
                size_t g = (size_t)((kb + 1) * 64 + row) * rstride + f4;
                cp_async16(Ks + row * AT_S + f4, kbase + g);
                cp_async16(Vs + row * AT_S + f4, vbase + g);
            }
        }
        cp_commit();
        cp_wait1();
        __syncthreads();

        const uint32_t* Ks = KV + (kb & 1) * 2 * AT_T;
        const uint32_t* Vs = Ks + AT_T;

        float s[8][4];
#pragma unroll
        for (int nt = 0; nt < 8; nt++)
#pragma unroll
            for (int j = 0; j < 4; j++) s[nt][j] = 0.0f;

#pragma unroll
        for (int kt = 0; kt < 8; kt++) {
            uint32_t af[4], bf[8][2];
            af[0] = Qs[(wrow + qr) * AT_S + kt * 8 + qc];
            af[1] = Qs[(wrow + qr + 8) * AT_S + kt * 8 + qc];
            af[2] = Qs[(wrow + qr) * AT_S + kt * 8 + qc + 4];
            af[3] = Qs[(wrow + qr + 8) * AT_S + kt * 8 + qc + 4];
#pragma unroll
            for (int nt = 0; nt < 8; nt++) {
                bf[nt][0] = Ks[(nt * 8 + qr) * AT_S + kt * 8 + qc];
                bf[nt][1] = Ks[(nt * 8 + qr) * AT_S + kt * 8 + qc + 4];
            }
#pragma unroll
            for (int nt = 0; nt < 8; nt++) mma_tf32(s[nt], af, bf[nt]);
        }

        if (kb == qt) {
            int r0 = wrow + qr, r1 = r0 + 8;
#pragma unroll
            for (int nt = 0; nt < 8; nt++) {
                int c0 = nt * 8 + (qc << 1), c1 = c0 + 1;
                if (c0 > r0) s[nt][0] = -1e30f;
                if (c1 > r0) s[nt][1] = -1e30f;
                if (c0 > r1) s[nt][2] = -1e30f;
                if (c1 > r1) s[nt][3] = -1e30f;
            }
        }

        float tm0 = -1e30f, tm1 = -1e30f;
#pragma unroll
        for (int nt = 0; nt < 8; nt++) {
            tm0 = fmaxf(tm0, fmaxf(s[nt][0], s[nt][1]));
            tm1 = fmaxf(tm1, fmaxf(s[nt][2], s[nt][3]));
        }
        tm0 = fmaxf(tm0, __shfl_xor_sync(0xffffffffu, tm0, 1));
        tm0 = fmaxf(tm0, __shfl_xor_sync(0xffffffffu, tm0, 2));
        tm1 = fmaxf(tm1, __shfl_xor_sync(0xffffffffu, tm1, 1));
        tm1 = fmaxf(tm1, __shfl_xor_sync(0xffffffffu, tm1, 2));

        float mn0 = fmaxf(m0, tm0), mn1 = fmaxf(m1, tm1);
        float sc0 = __expf(m0 - mn0), sc1 = __expf(m1 - mn1);
        float rs0 = 0.0f, rs1 = 0.0f;
#pragma unroll
        for (int nt = 0; nt < 8; nt++) {
            s[nt][0] = __expf(s[nt][0] - mn0);
            s[nt][1] = __expf(s[nt][1] - mn0);
            s[nt][2] = __expf(s[nt][2] - mn1);
            s[nt][3] = __expf(s[nt][3] - mn1);
            rs0 += s[nt][0] + s[nt][1];
            rs1 += s[nt][2] + s[nt][3];
        }
        rs0 += __shfl_xor_sync(0xffffffffu, rs0, 1);
        rs0 += __shfl_xor_sync(0xffffffffu, rs0, 2);
        rs1 += __shfl_xor_sync(0xffffffffu, rs1, 1);
        rs1 += __shfl_xor_sync(0xffffffffu, rs1, 2);
        l0 = l0 * sc0 + rs0;  l1 = l1 * sc1 + rs1;
        m0 = mn0;  m1 = mn1;
#pragma unroll
        for (int nt = 0; nt < 8; nt++) {
            o[nt][0] *= sc0;  o[nt][1] *= sc0;
            o[nt][2] *= sc1;  o[nt][3] *= sc1;
        }

#pragma unroll
        for (int nt = 0; nt < 8; nt++) {
            int c = nt * 8 + (qc << 1);
            Ps[(wrow + qr) * AT_S + c]         = f2tf(s[nt][0]);
            Ps[(wrow + qr) * AT_S + c + 1]     = f2tf(s[nt][1]);
            Ps[(wrow + qr + 8) * AT_S + c]     = f2tf(s[nt][2]);
            Ps[(wrow + qr + 8) * AT_S + c + 1] = f2tf(s[nt][3]);
        }
        __syncwarp();

#pragma unroll
        for (int kt = 0; kt < 8; kt++) {
            uint32_t af[4], bf[8][2];
            af[0] = Ps[(wrow + qr) * AT_S + kt * 8 + qc];
            af[1] = Ps[(wrow + qr + 8) * AT_S + kt * 8 + qc];
            af[2] = Ps[(wrow + qr) * AT_S + kt * 8 + qc + 4];
            af[3] = Ps[(wrow + qr + 8) * AT_S + kt * 8 + qc + 4];
#pragma unroll
            for (int nt = 0; nt < 8; nt++) {
                bf[nt][0] = Vs[(kt * 8 + qc) * AT_S + nt * 8 + qr];
                bf[nt][1] = Vs[(kt * 8 + qc + 4) * AT_S + nt * 8 + qr];
            }
#pragma unroll
            for (int nt = 0; nt < 8; nt++) mma_tf32(o[nt], af, bf[nt]);
        }
    }

    float inv0 = 1.0f / l0, inv1 = 1.0f / l1;
    size_t zr0 = (size_t)(b * P_ + qt * 64 + wrow + qr) * M_ + h * D_;
    size_t zr1 = zr0 + (size_t)8 * M_;
#pragma unroll
    for (int nt = 0; nt < 8; nt++) {
        int c = nt * 8 + (qc << 1);
        *(uint2*)(Z + zr0 + c) = make_uint2(f2tf(o[nt][0] * inv0), f2tf(o[nt][1] * inv0));
        *(uint2*)(Z + zr1 + c) = make_uint2(f2tf(o[nt][2] * inv1), f2tf(o[nt][3] * inv1));
    }
}

// ---------------------------------------------------------------------------
extern "C" void kernel_launch(void* const* d_in, const int* in_sizes, int n_in,
                              void* d_out, int out_size)
{
    const float* x      = (const float*)d_in[0];
    const float* W_attn = (const float*)d_in[1];
    const float* b_attn = (const float*)d_in[2];
    const float* W_proj = (const float*)d_in[3];
    const float* b_proj = (const float*)d_in[4];

    uint32_t *xt, *wa, *wp, *qkv, *z;
    cudaGetSymbolAddress((void**)&xt,  g_xt);
    cudaGetSymbolAddress((void**)&wa,  g_wa);
    cudaGetSymbolAddress((void**)&wp,  g_wp);
    cudaGetSymbolAddress((void**)&qkv, g_qkv);
    cudaGetSymbolAddress((void**)&z,   g_z);

    cudaFuncSetAttribute(gemm_tf32<true>,  cudaFuncAttributeMaxDynamicSharedMemorySize, SMEM_GEMM);
    cudaFuncSetAttribute(gemm_tf32<false>, cudaFuncAttributeMaxDynamicSharedMemorySize, SMEM_GEMM);
    cudaFuncSetAttribute(attn_tf32, cudaFuncAttributeMaxDynamicSharedMemorySize, SMEM_ATTN);

    // 0) pre-convert inputs to tf32 bits
    {
        int n4x = NROWS * M_ / 4, n4a = M_ * QKV_N / 4, n4p = M_ * M_ / 4;
        cvt_tf32_kernel<<<(n4x + 255) / 256, 256>>>((const float4*)x, (uint4*)xt, n4x);
        cvt_tf32_kernel<<<(n4a + 255) / 256, 256>>>((const float4*)W_attn, (uint4*)wa, n4a);
        cvt_tf32_kernel<<<(n4p + 255) / 256, 256>>>((const float4*)W_proj, (uint4*)wp, n4p);
    }

    // 1) QKV projection (tf32 out)
    gemm_tf32<true><<<dim3(QKV_N / 128, NROWS / 128), 256, SMEM_GEMM>>>(xt, wa, b_attn, qkv, QKV_N, M_);

    // 2) Causal flash attention (tf32 in/out)
    attn_tf32<<<dim3(P_ / 64, H_, B_), 128, SMEM_ATTN>>>(qkv, z);

    // 3) Output projection (fp32 out)
    gemm_tf32<false><<<dim3(M_ / 128, NROWS / 128), 256, SMEM_GEMM>>>(z, wp, b_proj, (float*)d_out, M_, M_);
}

// round 15
// speedup vs baseline: 9.6784x; 1.7588x over previous
#include <cuda_runtime.h>
#include <cuda_fp16.h>
#include <stdint.h>

// Problem constants
#define B_   2
#define P_   2048
#define M_   1024
#define H_   16
#define D_   64
#define NROWS (B_ * P_)          // 4096
#define QKV_N (3 * M_)           // 3072

// Scratch (device globals), fp16
__device__ __align__(128) __half g_xh [(size_t)NROWS * M_];     // fp16(x)        [rows][K]
__device__ __align__(128) __half g_wa [(size_t)QKV_N * M_];     // fp16(W_attn^T) [N][K]
__device__ __align__(128) __half g_wp [(size_t)M_ * M_];        // fp16(W_proj^T) [N][K]
__device__ __align__(128) __half g_qkv[(size_t)NROWS * QKV_N];  // fp16 Q|K|V
__device__ __align__(128) __half g_z  [(size_t)NROWS * M_];     // fp16 attn out

// ---------------------------------------------------------------------------
// helpers
// ---------------------------------------------------------------------------
__device__ __forceinline__ uint32_t packh2(float a, float b) {
    __half2 h = __floats2half2_rn(a, b);
    return *(uint32_t*)&h;
}

// D(16x8,f32) += A(16x16,f16) * B(16x8,f16)
__device__ __forceinline__ void mma_f16(float* d, const uint32_t* a, const uint32_t* b) {
    asm volatile(
        "mma.sync.aligned.m16n8k16.row.col.f32.f16.f16.f32 "
        "{%0,%1,%2,%3}, {%4,%5,%6,%7}, {%8,%9}, {%0,%1,%2,%3};"
        : "+f"(d[0]), "+f"(d[1]), "+f"(d[2]), "+f"(d[3])
        : "r"(a[0]), "r"(a[1]), "r"(a[2]), "r"(a[3]), "r"(b[0]), "r"(b[1]));
}

// ldmatrix x4 transposed b16: 4 8x8 matrices -> B fragments
__device__ __forceinline__ void ldmx4t(uint32_t* r, uint32_t saddr) {
    asm volatile("ldmatrix.sync.aligned.m8n8.x4.trans.shared.b16 {%0,%1,%2,%3}, [%4];"
                 : "=r"(r[0]), "=r"(r[1]), "=r"(r[2]), "=r"(r[3]) : "r"(saddr));
}

__device__ __forceinline__ void cp_async16(void* smem_dst, const void* gmem_src) {
    uint32_t s = (uint32_t)__cvta_generic_to_shared(smem_dst);
    asm volatile("cp.async.cg.shared.global [%0], [%1], 16;" :: "r"(s), "l"(gmem_src));
}
__device__ __forceinline__ void cp_commit() { asm volatile("cp.async.commit_group;"); }
__device__ __forceinline__ void cp_wait1()  { asm volatile("cp.async.wait_group 1;" ::: "memory"); }

// ---------------------------------------------------------------------------
// Pre-pass: fp32 -> fp16 (plain + transposed variants)
// ---------------------------------------------------------------------------
__global__ __launch_bounds__(256) void cvt_h_kernel(const float4* __restrict__ in,
                                                    uint2* __restrict__ out, int n4)
{
    int i = blockIdx.x * blockDim.x + threadIdx.x;
    if (i < n4) {
        float4 v = in[i];
        out[i] = make_uint2(packh2(v.x, v.y), packh2(v.z, v.w));
    }
}

// out[n][k] = fp16(in[k][n]); in: [K][Ncols]
__global__ __launch_bounds__(256) void cvt_t_h_kernel(const float* __restrict__ in,
                                                      __half* __restrict__ out,
                                                      int K, int Ncols)
{
    __shared__ __half tile[32][33];
    int c0 = blockIdx.x * 32, r0 = blockIdx.y * 32;
    int tx = threadIdx.x & 31, ty = threadIdx.x >> 5;
    for (int i = ty; i < 32; i += 8)
        tile[i][tx] = __float2half_rn(in[(size_t)(r0 + i) * Ncols + c0 + tx]);
    __syncthreads();
    for (int i = ty; i < 32; i += 8)
        out[(size_t)(c0 + i) * K + r0 + tx] = tile[tx][i];
}

// ---------------------------------------------------------------------------
// fp16 GEMM: C[rows,N] = A[rows,K] @ Bt[N,K]^T + bias
// CTA 128x128, BK=32, 256 thr = 8 warps (2x4), warp tile 64x32, m16n8k16.
// Both tiles [128][40] halfs (row stride 40 -> frag word addr 20*qr+qc: CF).
// 3-stage cp.async ring.
// ---------------------------------------------------------------------------
#define A_S   40                    // halfs per row (32 data + 8 pad)
#define A_SZ  (128 * A_S)           // halfs per tile
#define STG_SZ (2 * A_SZ)
#define SMEM_GEMM (3 * STG_SZ * 2)  // 61440 B

__device__ __forceinline__ void gemm_load_stage(__half* As, __half* Bs,
                                                const __half* __restrict__ A,
                                                const __half* __restrict__ Bt,
                                                int brow, int bcol, int k0,
                                                int K, int t)
{
#pragma unroll
    for (int j = 0; j < 2; j++) {               // A: 128 rows x 4 16B-chunks
        int i = t + 256 * j;
        int r = i >> 2, c = i & 3;
        cp_async16(As + r * A_S + c * 8, A + (size_t)(brow + r) * K + k0 + c * 8);
    }
#pragma unroll
    for (int j = 0; j < 2; j++) {               // B: 128 n-rows x 4 chunks
        int i = t + 256 * j;
        int r = i >> 2, c = i & 3;
        cp_async16(Bs + r * A_S + c * 8, Bt + (size_t)(bcol + r) * K + k0 + c * 8);
    }
}

template <bool OUT_HALF>
__global__ __launch_bounds__(256, 2) void gemm_f16(const __half* __restrict__ A,
                                                   const __half* __restrict__ Bt,
                                                   const float* __restrict__ bias,
                                                   void* __restrict__ Cv,
                                                   int N, int K)
{
    extern __shared__ __half smg[];

    const int t = threadIdx.x, lane = t & 31, warp = t >> 5;
    const int wm = (warp >> 2) * 64;
    const int wn = (warp & 3) * 32;
    const int brow = blockIdx.y * 128, bcol = blockIdx.x * 128;
    const int qr = lane >> 2, qc = lane & 3;

    float acc[4][4][4];
#pragma unroll
    for (int mt = 0; mt < 4; mt++)
#pragma unroll
        for (int nt = 0; nt < 4; nt++)
#pragma unroll
            for (int j = 0; j < 4; j++) acc[mt][nt][j] = 0.0f;

    const int ntiles = K / 32;

    gemm_load_stage(smg, smg + A_SZ, A, Bt, brow, bcol, 0, K, t);
    cp_commit();
    gemm_load_stage(smg + STG_SZ, smg + STG_SZ + A_SZ, A, Bt, brow, bcol, 32, K, t);
    cp_commit();

    for (int kt = 0; kt < ntiles; kt++) {
        cp_wait1();
        __syncthreads();

        int nxt = kt + 2;
        if (nxt < ntiles) {
            __half* s = smg + (nxt % 3) * STG_SZ;
            gemm_load_stage(s, s + A_SZ, A, Bt, brow, bcol, nxt * 32, K, t);
        }
        cp_commit();

        const __half* Ac = smg + (kt % 3) * STG_SZ;
        const __half* Bc = Ac + A_SZ;

#pragma unroll
        for (int ks = 0; ks < 32; ks += 16) {
            uint32_t af[4][4], bf[4][2];
#pragma unroll
            for (int mt = 0; mt < 4; mt++) {
                const __half* ar = Ac + (wm + mt * 16 + qr) * A_S + ks + 2 * qc;
                af[mt][0] = *(const uint32_t*)(ar);
                af[mt][1] = *(const uint32_t*)(ar + 8 * A_S);
                af[mt][2] = *(const uint32_t*)(ar + 8);
                af[mt][3] = *(const uint32_t*)(ar + 8 * A_S + 8);
            }
#pragma unroll
            for (int nt = 0; nt < 4; nt++) {
                const __half* br = Bc + (wn + nt * 8 + qr) * A_S + ks + 2 * qc;
                bf[nt][0] = *(const uint32_t*)(br);
                bf[nt][1] = *(const uint32_t*)(br + 8);
            }
#pragma unroll
            for (int mt = 0; mt < 4; mt++)
#pragma unroll
                for (int nt = 0; nt < 4; nt++)
                    mma_f16(acc[mt][nt], af[mt], bf[nt]);
        }
        __syncthreads();
    }

    // Epilogue: c0/c1 rows qr, c2/c3 rows qr+8; cols 2*qc, 2*qc+1
#pragma unroll
    for (int mt = 0; mt < 4; mt++) {
        int r0 = brow + wm + mt * 16 + qr;
#pragma unroll
        for (int nt = 0; nt < 4; nt++) {
            int c0 = bcol + wn + nt * 8 + (qc << 1);
            float b0 = bias[c0], b1 = bias[c0 + 1];
            float v00 = acc[mt][nt][0] + b0, v01 = acc[mt][nt][1] + b1;
            float v10 = acc[mt][nt][2] + b0, v11 = acc[mt][nt][3] + b1;
            if (OUT_HALF) {
                __half* C = (__half*)Cv;
                *(uint32_t*)(C + (size_t)r0 * N + c0)       = packh2(v00, v01);
                *(uint32_t*)(C + (size_t)(r0 + 8) * N + c0) = packh2(v10, v11);
            } else {
                float* C = (float*)Cv;
                *(float2*)(C + (size_t)r0 * N + c0)       = make_float2(v00, v01);
                *(float2*)(C + (size_t)(r0 + 8) * N + c0) = make_float2(v10, v11);
            }
        }
    }
}

// ---------------------------------------------------------------------------
// Flash attention (causal), fp16 m16n8k16.
// CTA = (64-query tile, head, batch); 4 warps, each owns 16 query rows.
// Tiles [64][72] halfs (stride 72 -> frag word 4*qr+qc: conflict-free).
// S=QK^T: B-frag straight from K [key][d]. PV: B-frag via ldmatrix.x4.trans.
// K/V double-buffered with cp.async.
// NOTE: one K/V tile = 64 rows x 8 16B-chunks = 512 cp.asyncs = 128 thr x 4.
// ---------------------------------------------------------------------------
#define AT_S 72
#define AT_T (64 * AT_S)                       // halfs per tile (4608)
#define SMEM_ATTN ((2 + 4) * AT_T * 2)         // Qs,Ps + 2x(Ks,Vs) = 55296 B

__global__ __launch_bounds__(128) void attn_f16(const __half* __restrict__ qkv,
                                                __half* __restrict__ Z)
{
    extern __shared__ __half smh[];
    __half* Qs = smh;
    __half* Ps = smh + AT_T;
    __half* KV = smh + 2 * AT_T;   // buf b: K at b*2*AT_T, V at +AT_T

    const int qt = blockIdx.x, h = blockIdx.y, b = blockIdx.z;
    const int t = threadIdx.x, lane = t & 31, warp = t >> 5;
    const int wrow = warp * 16;
    const int qr = lane >> 2, qc = lane & 3;

    const size_t rstride = QKV_N;
    const __half* qbase = qkv + (size_t)(b * P_ + qt * 64) * rstride + h * D_;
    const __half* kbase = qkv + (size_t)b * P_ * rstride + M_ + h * D_;
    const __half* vbase = kbase + M_;

    // ldmatrix lane constants (4 matrices: m0 k0-7/n0-7, m1 k8-15/n0-7,
    // m2 k0-7/n8-15, m3 k8-15/n8-15)
    const int lrow = (lane & 7) + ((lane >> 3) & 1) * 8;
    const int lcol = ((lane >> 4) & 1) * 8;

    // Q tile: fp16 scaled by 1/8 (exact exponent shift)
    const __half2 s8 = __floats2half2_rn(0.125f, 0.125f);
    for (int i = t; i < 512; i += 128) {
        int r = i >> 3, c = (i & 7) * 8;
        uint4 u = *(const uint4*)(qbase + (size_t)r * rstride + c);
        __half2* hp = (__half2*)&u;
        hp[0] = __hmul2(hp[0], s8);
        hp[1] = __hmul2(hp[1], s8);
        hp[2] = __hmul2(hp[2], s8);
        hp[3] = __hmul2(hp[3], s8);
        *(uint4*)(&Qs[r * AT_S + c]) = u;
    }

    // Prefetch kb=0 (512 chunks: 128 thr x 4)
    {
        __half* Ks = KV;
        __half* Vs = KV + AT_T;
#pragma unroll
        for (int j = 0; j < 4; j++) {
            int i = t + 128 * j;
            int r = i >> 3, c = (i & 7) * 8;
            size_t g = (size_t)r * rstride + c;
            cp_async16(Ks + r * AT_S + c, kbase + g);
            cp_async16(Vs + r * AT_S + c, vbase + g);
        }
        cp_commit();
    }

    float m0 = -1e30f, m1 = -1e30f, l0 = 0.0f, l1 = 0.0f;
    float o[8][4];
#pragma unroll
    for (int nt = 0; nt < 8; nt++)
#pragma unroll
        for (int j = 0; j < 4; j++) o[nt][j] = 0.0f;

    for (int kb = 0; kb <= qt; kb++) {
        __syncthreads();
        if (kb + 1 <= qt) {
            __half* Ks = KV + ((kb + 1) & 1) * 2 * AT_T;
            __half* Vs = Ks + AT_T;
#pragma unroll
            for (int j = 0; j < 4; j++) {
                int i = t + 128 * j;
                int r = i >> 3, c = (i & 7) * 8;
                size_t g = (size_t)((kb + 1) * 64 + r) * rstride + c;
                cp_async16(Ks + r * AT_S + c, kbase + g);
                cp_async16(Vs + r * AT_S + c, vbase + g);
            }
        }
        cp_commit();
        cp_wait1();
        __syncthreads();

        const __half* Ks = KV + (kb & 1) * 2 * AT_T;
        const __half* Vs = Ks + AT_T;
        const uint32_t vs_s = (uint32_t)__cvta_generic_to_shared(Vs);

        // ---- S = Q K^T : 4 k-steps of 16 over d
        float s[8][4];
#pragma unroll
        for (int nt = 0; nt < 8; nt++)
#pragma unroll
            for (int j = 0; j < 4; j++) s[nt][j] = 0.0f;

#pragma unroll
        for (int kt = 0; kt < 4; kt++) {
            uint32_t af[4], bf[8][2];
            const __half* ar = Qs + (wrow + qr) * AT_S + kt * 16 + 2 * qc;
            af[0] = *(const uint32_t*)(ar);
            af[1] = *(const uint32_t*)(ar + 8 * AT_S);
            af[2] = *(const uint32_t*)(ar + 8);
            af[3] = *(const uint32_t*)(ar + 8 * AT_S + 8);
#pragma unroll
            for (int nt = 0; nt < 8; nt++) {
                const __half* kr = Ks + (nt * 8 + qr) * AT_S + kt * 16 + 2 * qc;
                bf[nt][0] = *(const uint32_t*)(kr);
                bf[nt][1] = *(const uint32_t*)(kr + 8);
            }
#pragma unroll
            for (int nt = 0; nt < 8; nt++) mma_f16(s[nt], af, bf[nt]);
        }

        if (kb == qt) {   // causal mask, tile-local coords
            int r0 = wrow + qr, r1 = r0 + 8;
#pragma unroll
            for (int nt = 0; nt < 8; nt++) {
                int c0 = nt * 8 + (qc << 1), c1 = c0 + 1;
                if (c0 > r0) s[nt][0] = -1e30f;
                if (c1 > r0) s[nt][1] = -1e30f;
                if (c0 > r1) s[nt][2] = -1e30f;
                if (c1 > r1) s[nt][3] = -1e30f;
            }
        }

        // ---- online softmax (quad reduction)
        float tm0 = -1e30f, tm1 = -1e30f;
#pragma unroll
        for (int nt = 0; nt < 8; nt++) {
            tm0 = fmaxf(tm0, fmaxf(s[nt][0], s[nt][1]));
            tm1 = fmaxf(tm1, fmaxf(s[nt][2], s[nt][3]));
        }
        tm0 = fmaxf(tm0, __shfl_xor_sync(0xffffffffu, tm0, 1));
        tm0 = fmaxf(tm0, __shfl_xor_sync(0xffffffffu, tm0, 2));
        tm1 = fmaxf(tm1, __shfl_xor_sync(0xffffffffu, tm1, 1));
        tm1 = fmaxf(tm1, __shfl_xor_sync(0xffffffffu, tm1, 2));

        float mn0 = fmaxf(m0, tm0), mn1 = fmaxf(m1, tm1);
        float sc0 = __expf(m0 - mn0), sc1 = __expf(m1 - mn1);
        float rs0 = 0.0f, rs1 = 0.0f;
#pragma unroll
        for (int nt = 0; nt < 8; nt++) {
            s[nt][0] = __expf(s[nt][0] - mn0);
            s[nt][1] = __expf(s[nt][1] - mn0);
            s[nt][2] = __expf(s[nt][2] - mn1);
            s[nt][3] = __expf(s[nt][3] - mn1);
            rs0 += s[nt][0] + s[nt][1];
            rs1 += s[nt][2] + s[nt][3];
        }
        rs0 += __shfl_xor_sync(0xffffffffu, rs0, 1);
        rs0 += __shfl_xor_sync(0xffffffffu, rs0, 2);
        rs1 += __shfl_xor_sync(0xffffffffu, rs1, 1);
        rs1 += __shfl_xor_sync(0xffffffffu, rs1, 2);
        l0 = l0 * sc0 + rs0;  l1 = l1 * sc1 + rs1;
        m0 = mn0;  m1 = mn1;
#pragma unroll
        for (int nt = 0; nt < 8; nt++) {
            o[nt][0] *= sc0;  o[nt][1] *= sc0;
            o[nt][2] *= sc1;  o[nt][3] *= sc1;
        }

        // ---- stage P as fp16 (packed .b32 stores), per-warp rows only
#pragma unroll
        for (int nt = 0; nt < 8; nt++) {
            int c = nt * 8 + (qc << 1);
            *(uint32_t*)(Ps + (wrow + qr) * AT_S + c)     = packh2(s[nt][0], s[nt][1]);
            *(uint32_t*)(Ps + (wrow + qr + 8) * AT_S + c) = packh2(s[nt][2], s[nt][3]);
        }
        __syncwarp();

        // ---- O += P @ V : 4 k-steps of 16 over keys; V frags via ldmatrix.trans
#pragma unroll
        for (int kt = 0; kt < 4; kt++) {
            uint32_t af[4];
            const __half* pr = Ps + (wrow + qr) * AT_S + kt * 16 + 2 * qc;
            af[0] = *(const uint32_t*)(pr);
            af[1] = *(const uint32_t*)(pr + 8 * AT_S);
            af[2] = *(const uint32_t*)(pr + 8);
            af[3] = *(const uint32_t*)(pr + 8 * AT_S + 8);

            uint32_t row_s = vs_s + ((kt * 16 + lrow) * AT_S + lcol) * 2;
#pragma unroll
            for (int np = 0; np < 4; np++) {      // covers nt = 2*np, 2*np+1
                uint32_t bv[4];
                ldmx4t(bv, row_s + np * 16 * 2);  // +16 halfs (d) per pair
                mma_f16(o[2 * np],     af, bv);
                mma_f16(o[2 * np + 1], af, bv + 2);
            }
        }
    }

    // ---- normalize + store Z as fp16
    float inv0 = 1.0f / l0, inv1 = 1.0f / l1;
    size_t zr0 = (size_t)(b * P_ + qt * 64 + wrow + qr) * M_ + h * D_;
    size_t zr1 = zr0 + (size_t)8 * M_;
#pragma unroll
    for (int nt = 0; nt < 8; nt++) {
        int c = nt * 8 + (qc << 1);
        *(uint32_t*)(Z + zr0 + c) = packh2(o[nt][0] * inv0, o[nt][1] * inv0);
        *(uint32_t*)(Z + zr1 + c) = packh2(o[nt][2] * inv1, o[nt][3] * inv1);
    }
}

// ---------------------------------------------------------------------------
extern "C" void kernel_launch(void* const* d_in, const int* in_sizes, int n_in,
                              void* d_out, int out_size)
{
    const float* x      = (const float*)d_in[0];
    const float* W_attn = (const float*)d_in[1];
    const float* b_attn = (const float*)d_in[2];
    const float* W_proj = (const float*)d_in[3];
    const float* b_proj = (const float*)d_in[4];

    __half *xh, *wa, *wp, *qkv, *z;
    cudaGetSymbolAddress((void**)&xh,  g_xh);
    cudaGetSymbolAddress((void**)&wa,  g_wa);
    cudaGetSymbolAddress((void**)&wp,  g_wp);
    cudaGetSymbolAddress((void**)&qkv, g_qkv);
    cudaGetSymbolAddress((void**)&z,   g_z);

    cudaFuncSetAttribute(gemm_f16<true>,  cudaFuncAttributeMaxDynamicSharedMemorySize, SMEM_GEMM);
    cudaFuncSetAttribute(gemm_f16<false>, cudaFuncAttributeMaxDynamicSharedMemorySize, SMEM_GEMM);
    cudaFuncSetAttribute(attn_f16, cudaFuncAttributeMaxDynamicSharedMemorySize, SMEM_ATTN);

    // 0) pre-pass: x -> fp16; weights -> transposed fp16 [N][K]
    {
        int n4x = NROWS * M_ / 4;
        cvt_h_kernel<<<(n4x + 255) / 256, 256>>>((const float4*)x, (uint2*)xh, n4x);
        cvt_t_h_kernel<<<dim3(QKV_N / 32, M_ / 32), 256>>>(W_attn, wa, M_, QKV_N);
        cvt_t_h_kernel<<<dim3(M_ / 32, M_ / 32),    256>>>(W_proj, wp, M_, M_);
    }

    // 1) QKV projection (fp16 out)
    gemm_f16<true><<<dim3(QKV_N / 128, NROWS / 128), 256, SMEM_GEMM>>>(xh, wa, b_attn, qkv, QKV_N, M_);

    // 2) Causal flash attention (fp16 in/out)
    attn_f16<<<dim3(P_ / 64, H_, B_), 128, SMEM_ATTN>>>(qkv, z);

    // 3) Output projection (fp32 out)
    gemm_f16<false><<<dim3(M_ / 128, NROWS / 128), 256, SMEM_GEMM>>>(z, wp, b_proj, (float*)d_out, M_, M_);
}